// round 12
// baseline (speedup 1.0000x reference)
#include <cuda_runtime.h>
#include <cuda_fp16.h>
#include <math.h>
#include <float.h>
#include <stdint.h>

#define B  4
#define C1 64
#define C2 256
#define C3 64
#define HW 9216
#define GOFF 97
#define HPAD 9410   // 97 guard + 9216 + 97 guard

// ---------------- scratch ----------------
__device__ float g_gl1[B*C1];
__device__ float g_gl2[B*C2*9];
__device__ float g_outA[B*C2*9];
__device__ float g_ocp2[B*C3*9];
__device__ float g_p4[B*3*8*3*256];                                // k4 partial maxes
__device__ __align__(16) unsigned short g_dyn1h[B*C2*C1];          // fp16 fc1 weights [b][o][c]
__device__ __align__(16) unsigned short g_xt[(size_t)B*HW*C1];     // fp16 x^T [b][l][c]
__device__ __align__(16) unsigned short g_hth[(size_t)B*HPAD*C2];  // fp16 h, [b][row][c]
__device__ __align__(16) unsigned short g_w2h[B*9*C3*C2];          // fp16 w, [b][tap][o][c]
__device__ __align__(16) float g_w2f[B*9*C3*C2];                   // fp32 w (edges)

// ---------------- helpers ----------------
__device__ __forceinline__ uint32_t smem_u32(const void* p) {
    uint32_t a;
    asm("{ .reg .u64 t; cvta.to.shared.u64 t, %1; cvt.u32.u64 %0, t; }" : "=r"(a) : "l"(p));
    return a;
}
__device__ __forceinline__ void cp16(uint32_t dst, const void* src) {
    asm volatile("cp.async.cg.shared.global [%0], [%1], 16;" :: "r"(dst), "l"(src));
}
__device__ __forceinline__ void ldm4(uint32_t* r, uint32_t addr) {
    asm volatile("ldmatrix.sync.aligned.m8n8.x4.shared.b16 {%0,%1,%2,%3}, [%4];"
        : "=r"(r[0]), "=r"(r[1]), "=r"(r[2]), "=r"(r[3]) : "r"(addr));
}
__device__ __forceinline__ void mma16816h(float* d, const uint32_t* a, uint32_t b0, uint32_t b1) {
    asm volatile("mma.sync.aligned.m16n8k16.row.col.f32.f16.f16.f32 "
        "{%0,%1,%2,%3}, {%4,%5,%6,%7}, {%8,%9}, {%0,%1,%2,%3};"
        : "+f"(d[0]), "+f"(d[1]), "+f"(d[2]), "+f"(d[3])
        : "r"(a[0]), "r"(a[1]), "r"(a[2]), "r"(a[3]), "r"(b0), "r"(b1));
}
__device__ __forceinline__ uint32_t sw128(uint32_t off) { return off ^ ((off >> 3) & 0x70); }
__device__ __forceinline__ uint32_t sw64(uint32_t off)  { return off ^ ((off >> 3) & 0x30); }

// ---------------- K0: zero guard rows of g_hth ----------------
__global__ void k0_zero() {
    int i = blockIdx.x * 256 + threadIdx.x;       // B*194*128 u32
    if (i >= B * 194 * 128) return;
    int u = i & 127;
    int r = (i >> 7) % 194;
    int b = i / (194 * 128);
    int row = (r < 97) ? r : (GOFF + HW + (r - 97));
    ((uint32_t*)g_hth)[((size_t)b * HPAD + row) * 128 + u] = 0;
}

// ---------------- K1: gl1 ----------------
__global__ void k1_gl1(const float* __restrict__ x) {
    int bc = blockIdx.x;
    const float* p = x + (size_t)bc * HW;
    float m = -FLT_MAX;
    for (int l = threadIdx.x; l < HW; l += 256) m = fmaxf(m, p[l]);
    #pragma unroll
    for (int off = 16; off; off >>= 1) m = fmaxf(m, __shfl_xor_sync(0xffffffffu, m, off));
    __shared__ float sm[8];
    if ((threadIdx.x & 31) == 0) sm[threadIdx.x >> 5] = m;
    __syncthreads();
    if (threadIdx.x == 0) {
        float r = sm[0];
        #pragma unroll
        for (int i = 1; i < 8; i++) r = fmaxf(r, sm[i]);
        g_gl1[bc] = r;
    }
}

// ---------------- K2: fc1 dynamic weights (fp16 out) ----------------
__global__ void k2_dyn1(const float* __restrict__ w1, const float* ce, const float* gd,
                        const float* gd2, const float* __restrict__ ci) {
    int b = blockIdx.x, t = threadIdx.x;
    __shared__ float s1[C1], sre[C1];
    float cev = ce[0], gdv = gd[0], gd2v = gd2[0];
    if (t < C1) {
        float r = fmaxf(g_gl1[b*C1 + t] * cev, 0.f);
        sre[t] = r; s1[t] = r * gdv;
    }
    __syncthreads();
    int p = t >> 5, o2 = t & 31;
    float v = 0.f;
    #pragma unroll
    for (int g = 0; g < 8; g++) v += sre[p*8+g] * ci[o2*8+g];
    float s2 = fmaxf(v, 0.f) * gd2v;
    for (int c = 0; c < C1; c++) {
        float s = s1[c] + s2;
        float w = w1[t*C1 + c] / (1.f + expf(-s));
        g_dyn1h[(b*C2 + t)*C1 + c] = __half_as_ushort(__float2half(w));
    }
}

// ---------------- KX: transpose x -> fp16 [b][l][c] ----------------
__global__ void kx_t(const float* __restrict__ x) {
    __shared__ float st[64][65];
    int b = blockIdx.y, l0 = blockIdx.x * 64;
    int t = threadIdx.x;
    for (int i = t; i < 4096; i += 256) {
        int c = i >> 6, l = i & 63;
        st[c][l] = x[(size_t)(b*C1 + c)*HW + l0 + l];
    }
    __syncthreads();
    for (int i = t; i < 1024; i += 256) {
        int l = i >> 4, q = i & 15;
        ushort4 v4;
        v4.x = __half_as_ushort(__float2half(st[q*4+0][l]));
        v4.y = __half_as_ushort(__float2half(st[q*4+1][l]));
        v4.z = __half_as_ushort(__float2half(st[q*4+2][l]));
        v4.w = __half_as_ushort(__float2half(st[q*4+3][l]));
        *(ushort4*)&g_xt[((size_t)(b*HW) + l0 + l)*64 + q*4] = v4;
    }
}

// ---------------- K3T: fc1 via fp16 mma + GELU -> fp16 transposed h ----------------
__global__ __launch_bounds__(256) void k3t() {
    __shared__ __align__(16) unsigned short sAB[12288];   // A 16KB | B 8KB; epilogue reuse
    int l0 = blockIdx.x * 128, og = blockIdx.y, b = blockIdx.z;
    int t = threadIdx.x;
    uint32_t aA = smem_u32(sAB), aB = aA + 16384;

    const unsigned short* xa = g_xt + ((size_t)(b*HW) + l0)*64;
    #pragma unroll
    for (int j = 0; j < 4; j++) {
        int i = t + j * 256;
        int row = i >> 3, u = i & 7;
        cp16(aA + sw128((uint32_t)(row*128 + u*16)), xa + (size_t)row*64 + u*8);
    }
    const unsigned short* wb = g_dyn1h + ((size_t)(b*C2 + og*64))*64;
    #pragma unroll
    for (int j = 0; j < 2; j++) {
        int i = t + j * 256;
        int row = i >> 3, u = i & 7;
        cp16(aB + sw128((uint32_t)(row*128 + u*16)), wb + (size_t)row*64 + u*8);
    }
    asm volatile("cp.async.commit_group;" ::: "memory");
    asm volatile("cp.async.wait_group 0;" ::: "memory");
    __syncthreads();

    int w = t >> 5, lane = t & 31;
    float acc[8][4];
    #pragma unroll
    for (int i = 0; i < 8; i++)
        #pragma unroll
        for (int j = 0; j < 4; j++) acc[i][j] = 0.f;

    #pragma unroll
    for (int kk = 0; kk < 4; kk++) {
        uint32_t aoff = sw128((uint32_t)((16*w + (lane & 15)) * 128 + kk * 32 + (lane >> 4) * 16));
        uint32_t a[4];
        ldm4(a, aA + aoff);
        #pragma unroll
        for (int p = 0; p < 4; p++) {
            uint32_t boff = sw128((uint32_t)((p*16 + (lane & 15)) * 128 + kk * 32 + (lane >> 4) * 16));
            uint32_t bb[4];
            ldm4(bb, aB + boff);
            mma16816h(acc[2*p],   a, bb[0], bb[2]);
            mma16816h(acc[2*p+1], a, bb[1], bb[3]);
        }
    }
    __syncthreads();

    unsigned short* sh16 = sAB;
    int r = lane >> 2, c2 = (lane & 3) * 2;
    #pragma unroll
    for (int p = 0; p < 4; p++)
        #pragma unroll
        for (int q = 0; q < 2; q++) {
            int n = p*16 + q*8 + c2;
            #pragma unroll
            for (int hv = 0; hv < 2; hv++) {
                int m = 16*w + r + hv*8;
                #pragma unroll
                for (int e = 0; e < 2; e++) {
                    float v = acc[2*p+q][hv*2 + e];
                    v = 0.5f * v * (1.f + erff(v * 0.70710678118654752f));
                    sh16[m*68 + n + e] = __half_as_ushort(__float2half(v));
                }
            }
        }
    __syncthreads();
    #pragma unroll
    for (int i = t; i < 2048; i += 256) {
        int row = i >> 4, q = i & 15;
        uint2 vh = *(const uint2*)&sh16[row*68 + q*4];
        ((uint2*)g_hth)[((size_t)b*HPAD + GOFF + l0 + row)*64 + og*16 + q] = vh;
    }
}

// ---------------- K4a: partial 3x3 adaptive max over fp16 h ----------------
__global__ void k4a_part() {
    int bx = blockIdx.x;                 // 24 = ybin(3) * ys(8)
    int b = blockIdx.y;
    int ybin = bx >> 3, ys = bx & 7;
    int y0 = ybin * 32 + ys * 4;
    int t = threadIdx.x;                 // c
    const unsigned short* base = g_hth + ((size_t)b * HPAD + GOFF) * 256 + t;
    float m[3] = {-FLT_MAX, -FLT_MAX, -FLT_MAX};
    #pragma unroll
    for (int yy = 0; yy < 4; yy++) {
        const unsigned short* rp = base + (size_t)(y0 + yy) * 96 * 256;
        #pragma unroll
        for (int xb = 0; xb < 3; xb++) {
            float mm = m[xb];
            #pragma unroll 8
            for (int xx = 0; xx < 32; xx++)
                mm = fmaxf(mm, __half2float(__ushort_as_half(rp[(size_t)(xb*32 + xx) * 256])));
            m[xb] = mm;
        }
    }
    #pragma unroll
    for (int xb = 0; xb < 3; xb++)
        g_p4[((((size_t)b*3 + ybin)*8 + ys)*3 + xb)*256 + t] = m[xb];
}

// ---------------- K4b: reduce partials -> gl2 ----------------
__global__ void k4b_red() {
    int bin = blockIdx.x;                // ybin*3 + xbin
    int b = blockIdx.y;
    int t = threadIdx.x;                 // c
    int ybin = bin / 3, xbin = bin % 3;
    float m = -FLT_MAX;
    #pragma unroll
    for (int ys = 0; ys < 8; ys++)
        m = fmaxf(m, g_p4[((((size_t)b*3 + ybin)*8 + ys)*3 + xbin)*256 + t]);
    g_gl2[(b*C2 + t)*9 + ybin*3 + xbin] = m;
}

// ---------------- K5a: fc2 gating scalars ----------------
__global__ void k5a(const float* __restrict__ ce_w, const float* __restrict__ gd_w,
                    const float* __restrict__ gd2_w, const float* __restrict__ ci_w) {
    int b = blockIdx.x, t = threadIdx.x;
    __shared__ float sre[C2][5];
    {
        float glv[9];
        #pragma unroll
        for (int k = 0; k < 9; k++) glv[k] = g_gl2[(b*C2 + t)*9 + k];
        float rc[5];
        #pragma unroll
        for (int n = 0; n < 5; n++) {
            float v = 0.f;
            #pragma unroll
            for (int k = 0; k < 9; k++) v += glv[k] * ce_w[n*9 + k];
            rc[n] = fmaxf(v, 0.f);
            sre[t][n] = rc[n];
        }
        #pragma unroll
        for (int k = 0; k < 9; k++) {
            float v = 0.f;
            #pragma unroll
            for (int n = 0; n < 5; n++) v += rc[n] * gd_w[k*5 + n];
            g_outA[(b*C2 + t)*9 + k] = v;
        }
    }
    __syncthreads();
    if (t < C3) {
        int p = t >> 1, o2 = t & 1;
        float v[5];
        #pragma unroll
        for (int n = 0; n < 5; n++) {
            float s = 0.f;
            #pragma unroll
            for (int g = 0; g < 8; g++) s += sre[p*8+g][n] * ci_w[o2*8 + g];
            v[n] = fmaxf(s, 0.f);
        }
        #pragma unroll
        for (int k = 0; k < 9; k++) {
            float s = 0.f;
            #pragma unroll
            for (int n = 0; n < 5; n++) s += v[n] * gd2_w[k*5 + n];
            g_ocp2[(b*C3 + t)*9 + k] = s;
        }
    }
}

// ---------------- K5b: fp16 + fp32 dynamic fc2 weights, [b][tap][o][c] ----------------
__global__ void k5b(const float* __restrict__ w2) {
    int idx = blockIdx.x * 256 + threadIdx.x;       // ((b*9+k)*64+o)*256 + c
    int c = idx & 255;
    int o = (idx >> 8) & 63;
    int t2 = idx >> 14;
    int k = t2 % 9, b = t2 / 9;
    float s = g_outA[(b*C2 + c)*9 + k] + g_ocp2[(b*C3 + o)*9 + k];
    float w = w2[(o*C2 + c)*9 + k] / (1.f + expf(-s));
    g_w2h[idx] = __half_as_ushort(__float2half(w));
    g_w2f[idx] = w;
}

// ---------------- K6: fc2 fp16 mma; tap-shared A staging; 512 threads / 16 warps ----------------
#define ABUF 28928                         // 452 rows x 64B (c=32)
#define BBUF 36864                         // 9 taps x 64 o x 64B
#define STG6 (ABUF + BBUF)                 // 65792 per stage, x2 = 131584
__device__ __forceinline__ void stage6(uint32_t base, const unsigned short* hh,
        int b, int l0, int cb, int t) {
    const unsigned short* ha = hh + (size_t)(l0 - 97) * 256 + cb * 32;
    #pragma unroll
    for (int j = 0; j < 4; j++) {
        int i = t + j * 512;
        if (i < 1808) {
            int row = i >> 2, u = i & 3;
            cp16(base + sw64((uint32_t)(row*64 + u*16)), ha + (size_t)row*256 + u*8);
        }
    }
    const unsigned short* wb = g_w2h + (size_t)b * 9 * 64 * 256 + cb * 32;
    #pragma unroll
    for (int j = 0; j < 5; j++) {
        int i = t + j * 512;                       // 0..2303
        if (i < 2304) {
            int row2 = i >> 2, u = i & 3;          // row2 = tap*64 + o
            int tap = row2 >> 6, o = row2 & 63;
            cp16(base + ABUF + tap*4096 + sw64((uint32_t)(o*64 + u*16)),
                 wb + (size_t)row2 * 256 + u*8);
        }
    }
}

__global__ __launch_bounds__(512, 1) void k6_fc2(float* __restrict__ out) {
    extern __shared__ __align__(128) unsigned char sdy[];
    uint32_t base0 = smem_u32(sdy);
    int tile = blockIdx.x, b = blockIdx.y;
    int l0 = tile * 256, t = threadIdx.x;
    int w = t >> 5, lane = t & 31;       // 16 warps, warp owns m16: rows 16*w

    const unsigned short* hh = g_hth + ((size_t)b * HPAD + GOFF) * 256;

    float acc[8][4];
    #pragma unroll
    for (int i = 0; i < 8; i++)
        #pragma unroll
        for (int j = 0; j < 4; j++) acc[i][j] = 0.f;

    stage6(base0, hh, b, l0, 0, t);
    asm volatile("cp.async.commit_group;" ::: "memory");

    for (int cb = 0; cb < 8; cb++) {
        if (cb < 7) {
            stage6(base0 + ((cb + 1) & 1) * STG6, hh, b, l0, cb + 1, t);
            asm volatile("cp.async.commit_group;" ::: "memory");
            asm volatile("cp.async.wait_group 1;" ::: "memory");
        } else {
            asm volatile("cp.async.wait_group 0;" ::: "memory");
        }
        __syncthreads();
        uint32_t aA = base0 + (cb & 1) * STG6;
        uint32_t aB0 = aA + ABUF;
        #pragma unroll
        for (int tap = 0; tap < 9; tap++) {
            const int d = (tap / 3) * 96 + (tap % 3);
            #pragma unroll
            for (int kk = 0; kk < 2; kk++) {
                uint32_t a[4];
                uint32_t aoff = sw64((uint32_t)((16*w + (lane & 15) + d) * 64
                                                + kk * 32 + (lane >> 4) * 16));
                ldm4(a, aA + aoff);
                #pragma unroll
                for (int p = 0; p < 4; p++) {
                    uint32_t boff = aB0 + tap*4096
                        + sw64((uint32_t)((p*16 + (lane & 15)) * 64 + kk * 32 + (lane >> 4) * 16));
                    uint32_t bb[4];
                    ldm4(bb, boff);
                    mma16816h(acc[2*p],   a, bb[0], bb[2]);
                    mma16816h(acc[2*p+1], a, bb[1], bb[3]);
                }
            }
        }
        __syncthreads();
    }

    // epilogue: frag -> smem [o][l] stride 260 (conflict-free) -> gmem
    float* sD = (float*)sdy;                           // 64 x 260 floats (66.6KB)
    int r = lane >> 2, c2 = (lane & 3) * 2;
    int lbase = 16*w;
    #pragma unroll
    for (int q = 0; q < 8; q++) {
        int o = q * 8 + c2;
        sD[(o    ) * 260 + lbase + r    ] = acc[q][0];
        sD[(o + 1) * 260 + lbase + r    ] = acc[q][1];
        sD[(o    ) * 260 + lbase + r + 8] = acc[q][2];
        sD[(o + 1) * 260 + lbase + r + 8] = acc[q][3];
    }
    __syncthreads();
    float* ob = out + (size_t)b * C3 * HW + l0;
    #pragma unroll 4
    for (int i = t; i < 16384; i += 512)
        ob[(size_t)(i >> 8) * HW + (i & 255)] = sD[(i >> 8) * 260 + (i & 255)];
}

// ---------------- K7: exact edge columns; one warp per (y, side, b) ----------------
__global__ void k7_edges(float* __restrict__ out) {
    int y = blockIdx.x, side = blockIdx.y, b = blockIdx.z;
    int lane = threadIdx.x;
    int xbase = side ? 94 : 0, x = side ? 95 : 0;
    int dx0 = side ? 0 : 1;

    float hv[6][8];
    #pragma unroll
    for (int dy = 0; dy < 3; dy++)
        #pragma unroll
        for (int xxi = 0; xxi < 2; xxi++) {
            int l = (y + dy - 1) * 96 + xbase + xxi;
            const unsigned short* hp = g_hth + ((size_t)b * HPAD + GOFF + l) * 256 + lane * 8;
            uint4 uh = *(const uint4*)hp;
            float* hd = hv[dy*2 + xxi];
            hd[0] = __half2float(__ushort_as_half((unsigned short)(uh.x & 0xFFFF)));
            hd[1] = __half2float(__ushort_as_half((unsigned short)(uh.x >> 16)));
            hd[2] = __half2float(__ushort_as_half((unsigned short)(uh.y & 0xFFFF)));
            hd[3] = __half2float(__ushort_as_half((unsigned short)(uh.y >> 16)));
            hd[4] = __half2float(__ushort_as_half((unsigned short)(uh.z & 0xFFFF)));
            hd[5] = __half2float(__ushort_as_half((unsigned short)(uh.z >> 16)));
            hd[6] = __half2float(__ushort_as_half((unsigned short)(uh.w & 0xFFFF)));
            hd[7] = __half2float(__ushort_as_half((unsigned short)(uh.w >> 16)));
        }

    for (int o = 0; o < 64; o++) {
        float acc = 0.f;
        #pragma unroll
        for (int dy = 0; dy < 3; dy++)
            #pragma unroll
            for (int dxi = 0; dxi < 2; dxi++) {
                int tap = dy*3 + dx0 + dxi;
                const float* wf = g_w2f + ((size_t)((b*9 + tap)*64 + o))*256 + lane*8;
                float4 w0 = ((const float4*)wf)[0];
                float4 w1 = ((const float4*)wf)[1];
                const float* hd = hv[dy*2 + dxi];
                acc += hd[0]*w0.x + hd[1]*w0.y + hd[2]*w0.z + hd[3]*w0.w
                     + hd[4]*w1.x + hd[5]*w1.y + hd[6]*w1.z + hd[7]*w1.w;
            }
        #pragma unroll
        for (int off = 16; off; off >>= 1) acc += __shfl_xor_sync(0xffffffffu, acc, off);
        if (lane == 0) out[((size_t)b*C3 + o)*HW + y*96 + x] = acc;
    }
}

// ---------------- launch ----------------
extern "C" void kernel_launch(void* const* d_in, const int* in_sizes, int n_in,
                              void* d_out, int out_size) {
    const float* x     = (const float*)d_in[0];
    const float* w1    = (const float*)d_in[1];
    const float* f1ce  = (const float*)d_in[2];
    const float* f1gd  = (const float*)d_in[3];
    const float* f1gd2 = (const float*)d_in[4];
    const float* f1ci  = (const float*)d_in[5];
    const float* w2    = (const float*)d_in[6];
    const float* f2ce  = (const float*)d_in[7];
    const float* f2gd  = (const float*)d_in[8];
    const float* f2gd2 = (const float*)d_in[9];
    const float* f2ci  = (const float*)d_in[10];
    float* out = (float*)d_out;

    cudaFuncSetAttribute(k6_fc2, cudaFuncAttributeMaxDynamicSharedMemorySize, 2*STG6);

    k1_gl1<<<B*C1, 256>>>(x);
    k2_dyn1<<<B, 256>>>(w1, f1ce, f1gd, f1gd2, f1ci);
    kx_t<<<dim3(HW/64, B), 256>>>(x);
    k3t<<<dim3(HW/128, 4, B), 256>>>();
    k0_zero<<<(B*194*128 + 255)/256, 256>>>();
    k4a_part<<<dim3(24, B), 256>>>();
    k4b_red<<<dim3(9, B), 256>>>();
    k5a<<<B, 256>>>(f2ce, f2gd, f2gd2, f2ci);
    k5b<<<(B*9*C3*C2)/256, 256>>>(w2);
    k6_fc2<<<dim3(36, B), 512, 2*STG6>>>(out);
    k7_edges<<<dim3(96, 2, B), 32>>>(out);
}

// round 13
// speedup vs baseline: 1.7279x; 1.7279x over previous
#include <cuda_runtime.h>
#include <cuda_fp16.h>
#include <math.h>
#include <float.h>
#include <stdint.h>

#define B  4
#define C1 64
#define C2 256
#define C3 64
#define HW 9216
#define WP 98        // padded row stride (96 real + 2 zero pad)
#define LP 9408      // 96*98 padded length
#define GOFF 99      // top guard rows
#define HPAD 9792    // 99 guard + 9408 + 285 guard

// ---------------- scratch ----------------
__device__ float g_gl1[B*C1];
__device__ float g_gl2[B*C2*9];
__device__ float g_outA[B*C2*9];
__device__ float g_ocp2[B*C3*9];
__device__ float g_p4[B*3*8*3*256];                                // k4 partial maxes
__device__ __align__(16) unsigned short g_dyn1h[B*C2*C1];          // fp16 fc1 weights [b][o][c]
__device__ __align__(16) unsigned short g_xt[(size_t)B*HW*C1];     // fp16 x^T [b][l][c]
__device__ __align__(16) unsigned short g_hth[(size_t)B*HPAD*C2];  // fp16 h, [b][lp_row][c]
__device__ __align__(16) unsigned short g_w2h[B*9*C3*C2];          // fp16 w, [b][tap][o][c]

// ---------------- helpers ----------------
__device__ __forceinline__ uint32_t smem_u32(const void* p) {
    uint32_t a;
    asm("{ .reg .u64 t; cvta.to.shared.u64 t, %1; cvt.u32.u64 %0, t; }" : "=r"(a) : "l"(p));
    return a;
}
__device__ __forceinline__ void cp16(uint32_t dst, const void* src) {
    asm volatile("cp.async.cg.shared.global [%0], [%1], 16;" :: "r"(dst), "l"(src));
}
__device__ __forceinline__ void ldm4(uint32_t* r, uint32_t addr) {
    asm volatile("ldmatrix.sync.aligned.m8n8.x4.shared.b16 {%0,%1,%2,%3}, [%4];"
        : "=r"(r[0]), "=r"(r[1]), "=r"(r[2]), "=r"(r[3]) : "r"(addr));
}
__device__ __forceinline__ void mma16816h(float* d, const uint32_t* a, uint32_t b0, uint32_t b1) {
    asm volatile("mma.sync.aligned.m16n8k16.row.col.f32.f16.f16.f32 "
        "{%0,%1,%2,%3}, {%4,%5,%6,%7}, {%8,%9}, {%0,%1,%2,%3};"
        : "+f"(d[0]), "+f"(d[1]), "+f"(d[2]), "+f"(d[3])
        : "r"(a[0]), "r"(a[1]), "r"(a[2]), "r"(a[3]), "r"(b0), "r"(b1));
}
__device__ __forceinline__ uint32_t sw128(uint32_t off) { return off ^ ((off >> 3) & 0x70); }
__device__ __forceinline__ uint32_t sw64(uint32_t off)  { return off ^ ((off >> 3) & 0x30); }

// ---------------- K0: zero guard rows + x-pad columns of g_hth ----------------
// special rows per b: 99 top guard + 192 pad rows (96 y * 2) + 285 bottom guard = 576
__global__ void k0_zero() {
    int i = blockIdx.x * 256 + threadIdx.x;       // over B*576*128 u32
    if (i >= B * 576 * 128) return;
    int u = i & 127;
    int rr = (i >> 7) % 576;
    int b = i / (576 * 128);
    int row;
    if (rr < 99) row = rr;
    else if (rr < 291) {
        int k = rr - 99;
        row = GOFF + (k >> 1) * WP + 96 + (k & 1);
    } else {
        row = GOFF + LP + (rr - 291);
    }
    ((uint32_t*)g_hth)[((size_t)b * HPAD + row) * 128 + u] = 0;
}

// ---------------- K1: gl1 ----------------
__global__ void k1_gl1(const float* __restrict__ x) {
    int bc = blockIdx.x;
    const float* p = x + (size_t)bc * HW;
    float m = -FLT_MAX;
    for (int l = threadIdx.x; l < HW; l += 256) m = fmaxf(m, p[l]);
    #pragma unroll
    for (int off = 16; off; off >>= 1) m = fmaxf(m, __shfl_xor_sync(0xffffffffu, m, off));
    __shared__ float sm[8];
    if ((threadIdx.x & 31) == 0) sm[threadIdx.x >> 5] = m;
    __syncthreads();
    if (threadIdx.x == 0) {
        float r = sm[0];
        #pragma unroll
        for (int i = 1; i < 8; i++) r = fmaxf(r, sm[i]);
        g_gl1[bc] = r;
    }
}

// ---------------- K2: fc1 dynamic weights (fp16 out) ----------------
__global__ void k2_dyn1(const float* __restrict__ w1, const float* ce, const float* gd,
                        const float* gd2, const float* __restrict__ ci) {
    int b = blockIdx.x, t = threadIdx.x;
    __shared__ float s1[C1], sre[C1];
    float cev = ce[0], gdv = gd[0], gd2v = gd2[0];
    if (t < C1) {
        float r = fmaxf(g_gl1[b*C1 + t] * cev, 0.f);
        sre[t] = r; s1[t] = r * gdv;
    }
    __syncthreads();
    int p = t >> 5, o2 = t & 31;
    float v = 0.f;
    #pragma unroll
    for (int g = 0; g < 8; g++) v += sre[p*8+g] * ci[o2*8+g];
    float s2 = fmaxf(v, 0.f) * gd2v;
    for (int c = 0; c < C1; c++) {
        float s = s1[c] + s2;
        float w = w1[t*C1 + c] / (1.f + expf(-s));
        g_dyn1h[(b*C2 + t)*C1 + c] = __half_as_ushort(__float2half(w));
    }
}

// ---------------- KX: transpose x -> fp16 [b][l][c] ----------------
__global__ void kx_t(const float* __restrict__ x) {
    __shared__ float st[64][65];
    int b = blockIdx.y, l0 = blockIdx.x * 64;
    int t = threadIdx.x;
    for (int i = t; i < 4096; i += 256) {
        int c = i >> 6, l = i & 63;
        st[c][l] = x[(size_t)(b*C1 + c)*HW + l0 + l];
    }
    __syncthreads();
    for (int i = t; i < 1024; i += 256) {
        int l = i >> 4, q = i & 15;
        ushort4 v4;
        v4.x = __half_as_ushort(__float2half(st[q*4+0][l]));
        v4.y = __half_as_ushort(__float2half(st[q*4+1][l]));
        v4.z = __half_as_ushort(__float2half(st[q*4+2][l]));
        v4.w = __half_as_ushort(__float2half(st[q*4+3][l]));
        *(ushort4*)&g_xt[((size_t)(b*HW) + l0 + l)*64 + q*4] = v4;
    }
}

// ---------------- K3T: fc1 via fp16 mma + GELU -> fp16 padded-transposed h ----------------
__global__ __launch_bounds__(256) void k3t() {
    __shared__ __align__(16) unsigned short sAB[12288];   // A 16KB | B 8KB; epilogue reuse
    int l0 = blockIdx.x * 128, og = blockIdx.y, b = blockIdx.z;
    int t = threadIdx.x;
    uint32_t aA = smem_u32(sAB), aB = aA + 16384;

    const unsigned short* xa = g_xt + ((size_t)(b*HW) + l0)*64;
    #pragma unroll
    for (int j = 0; j < 4; j++) {
        int i = t + j * 256;
        int row = i >> 3, u = i & 7;
        cp16(aA + sw128((uint32_t)(row*128 + u*16)), xa + (size_t)row*64 + u*8);
    }
    const unsigned short* wb = g_dyn1h + ((size_t)(b*C2 + og*64))*64;
    #pragma unroll
    for (int j = 0; j < 2; j++) {
        int i = t + j * 256;
        int row = i >> 3, u = i & 7;
        cp16(aB + sw128((uint32_t)(row*128 + u*16)), wb + (size_t)row*64 + u*8);
    }
    asm volatile("cp.async.commit_group;" ::: "memory");
    asm volatile("cp.async.wait_group 0;" ::: "memory");
    __syncthreads();

    int w = t >> 5, lane = t & 31;
    float acc[8][4];
    #pragma unroll
    for (int i = 0; i < 8; i++)
        #pragma unroll
        for (int j = 0; j < 4; j++) acc[i][j] = 0.f;

    #pragma unroll
    for (int kk = 0; kk < 4; kk++) {
        uint32_t aoff = sw128((uint32_t)((16*w + (lane & 15)) * 128 + kk * 32 + (lane >> 4) * 16));
        uint32_t a[4];
        ldm4(a, aA + aoff);
        #pragma unroll
        for (int p = 0; p < 4; p++) {
            uint32_t boff = sw128((uint32_t)((p*16 + (lane & 15)) * 128 + kk * 32 + (lane >> 4) * 16));
            uint32_t bb[4];
            ldm4(bb, aB + boff);
            mma16816h(acc[2*p],   a, bb[0], bb[2]);
            mma16816h(acc[2*p+1], a, bb[1], bb[3]);
        }
    }
    __syncthreads();

    unsigned short* sh16 = sAB;
    int r = lane >> 2, c2 = (lane & 3) * 2;
    #pragma unroll
    for (int p = 0; p < 4; p++)
        #pragma unroll
        for (int q = 0; q < 2; q++) {
            int n = p*16 + q*8 + c2;
            #pragma unroll
            for (int hv = 0; hv < 2; hv++) {
                int m = 16*w + r + hv*8;
                #pragma unroll
                for (int e = 0; e < 2; e++) {
                    float v = acc[2*p+q][hv*2 + e];
                    v = 0.5f * v * (1.f + erff(v * 0.70710678118654752f));
                    sh16[m*68 + n + e] = __half_as_ushort(__float2half(v));
                }
            }
        }
    __syncthreads();
    #pragma unroll
    for (int i = t; i < 2048; i += 256) {
        int row = i >> 4, q = i & 15;
        uint2 vh = *(const uint2*)&sh16[row*68 + q*4];
        int l = l0 + row;
        int y = l / 96;
        int lp = y * WP + (l - y * 96);
        ((uint2*)g_hth)[((size_t)b*HPAD + GOFF + lp)*64 + og*16 + q] = vh;
    }
}

// ---------------- K4a: partial 3x3 adaptive max over fp16 h (stride WP) ----------------
__global__ void k4a_part() {
    int bx = blockIdx.x;                 // 24 = ybin(3) * ys(8)
    int b = blockIdx.y;
    int ybin = bx >> 3, ys = bx & 7;
    int y0 = ybin * 32 + ys * 4;
    int t = threadIdx.x;                 // c
    const unsigned short* base = g_hth + ((size_t)b * HPAD + GOFF) * 256 + t;
    float m[3] = {-FLT_MAX, -FLT_MAX, -FLT_MAX};
    #pragma unroll
    for (int yy = 0; yy < 4; yy++) {
        const unsigned short* rp = base + (size_t)(y0 + yy) * WP * 256;
        #pragma unroll
        for (int xb = 0; xb < 3; xb++) {
            float mm = m[xb];
            #pragma unroll 8
            for (int xx = 0; xx < 32; xx++)
                mm = fmaxf(mm, __half2float(__ushort_as_half(rp[(size_t)(xb*32 + xx) * 256])));
            m[xb] = mm;
        }
    }
    #pragma unroll
    for (int xb = 0; xb < 3; xb++)
        g_p4[((((size_t)b*3 + ybin)*8 + ys)*3 + xb)*256 + t] = m[xb];
}

// ---------------- K4b: reduce partials -> gl2 ----------------
__global__ void k4b_red() {
    int bin = blockIdx.x;                // ybin*3 + xbin
    int b = blockIdx.y;
    int t = threadIdx.x;
    int ybin = bin / 3, xbin = bin % 3;
    float m = -FLT_MAX;
    #pragma unroll
    for (int ys = 0; ys < 8; ys++)
        m = fmaxf(m, g_p4[((((size_t)b*3 + ybin)*8 + ys)*3 + xbin)*256 + t]);
    g_gl2[(b*C2 + t)*9 + ybin*3 + xbin] = m;
}

// ---------------- K5a: fc2 gating scalars ----------------
__global__ void k5a(const float* __restrict__ ce_w, const float* __restrict__ gd_w,
                    const float* __restrict__ gd2_w, const float* __restrict__ ci_w) {
    int b = blockIdx.x, t = threadIdx.x;
    __shared__ float sre[C2][5];
    {
        float glv[9];
        #pragma unroll
        for (int k = 0; k < 9; k++) glv[k] = g_gl2[(b*C2 + t)*9 + k];
        float rc[5];
        #pragma unroll
        for (int n = 0; n < 5; n++) {
            float v = 0.f;
            #pragma unroll
            for (int k = 0; k < 9; k++) v += glv[k] * ce_w[n*9 + k];
            rc[n] = fmaxf(v, 0.f);
            sre[t][n] = rc[n];
        }
        #pragma unroll
        for (int k = 0; k < 9; k++) {
            float v = 0.f;
            #pragma unroll
            for (int n = 0; n < 5; n++) v += rc[n] * gd_w[k*5 + n];
            g_outA[(b*C2 + t)*9 + k] = v;
        }
    }
    __syncthreads();
    if (t < C3) {
        int p = t >> 1, o2 = t & 1;
        float v[5];
        #pragma unroll
        for (int n = 0; n < 5; n++) {
            float s = 0.f;
            #pragma unroll
            for (int g = 0; g < 8; g++) s += sre[p*8+g][n] * ci_w[o2*8 + g];
            v[n] = fmaxf(s, 0.f);
        }
        #pragma unroll
        for (int k = 0; k < 9; k++) {
            float s = 0.f;
            #pragma unroll
            for (int n = 0; n < 5; n++) s += v[n] * gd2_w[k*5 + n];
            g_ocp2[(b*C3 + t)*9 + k] = s;
        }
    }
}

// ---------------- K5b: fp16 dynamic fc2 weights, [b][tap][o][c] ----------------
__global__ void k5b(const float* __restrict__ w2) {
    int idx = blockIdx.x * 256 + threadIdx.x;       // ((b*9+k)*64+o)*256 + c
    int c = idx & 255;
    int o = (idx >> 8) & 63;
    int t2 = idx >> 14;
    int k = t2 % 9, b = t2 / 9;
    float s = g_outA[(b*C2 + c)*9 + k] + g_ocp2[(b*C3 + o)*9 + k];
    float w = w2[(o*C2 + c)*9 + k] / (1.f + expf(-s));
    g_w2h[idx] = __half_as_ushort(__float2half(w));
}

// ---------------- K6: fc2 fp16 mma; padded-stride shifts (exact), 37 tiles x B = 1 wave ----------------
#define ABUF 29056                         // 454 rows x 64B (c=32)
#define BBUF 36864                         // 9 taps x 64 o x 64B
#define STG6 (ABUF + BBUF)                 // 65920 per stage, x2 = 131840
__device__ __forceinline__ void stage6(uint32_t base, const unsigned short* hh,
        int b, int l0, int cb, int t) {
    const unsigned short* ha = hh + (size_t)(l0 - GOFF) * 256 + cb * 32;
    #pragma unroll
    for (int j = 0; j < 4; j++) {
        int i = t + j * 512;
        if (i < 1816) {                    // 454 rows x 4 chunks
            int row = i >> 2, u = i & 3;
            cp16(base + sw64((uint32_t)(row*64 + u*16)), ha + (size_t)row*256 + u*8);
        }
    }
    const unsigned short* wb = g_w2h + (size_t)b * 9 * 64 * 256 + cb * 32;
    #pragma unroll
    for (int j = 0; j < 5; j++) {
        int i = t + j * 512;                       // 0..2303
        if (i < 2304) {
            int row2 = i >> 2, u = i & 3;          // row2 = tap*64 + o
            int tap = row2 >> 6, o = row2 & 63;
            cp16(base + ABUF + tap*4096 + sw64((uint32_t)(o*64 + u*16)),
                 wb + (size_t)row2 * 256 + u*8);
        }
    }
}

__global__ __launch_bounds__(512, 1) void k6_fc2(float* __restrict__ out) {
    extern __shared__ __align__(128) unsigned char sdy[];
    uint32_t base0 = smem_u32(sdy);
    int tile = blockIdx.x, b = blockIdx.y;
    int l0 = tile * 256, t = threadIdx.x;
    int w = t >> 5, lane = t & 31;       // 16 warps, warp owns m16

    const unsigned short* hh = g_hth + ((size_t)b * HPAD + GOFF) * 256;

    float acc[8][4];
    #pragma unroll
    for (int i = 0; i < 8; i++)
        #pragma unroll
        for (int j = 0; j < 4; j++) acc[i][j] = 0.f;

    stage6(base0, hh, b, l0, 0, t);
    asm volatile("cp.async.commit_group;" ::: "memory");

    for (int cb = 0; cb < 8; cb++) {
        if (cb < 7) {
            stage6(base0 + ((cb + 1) & 1) * STG6, hh, b, l0, cb + 1, t);
            asm volatile("cp.async.commit_group;" ::: "memory");
            asm volatile("cp.async.wait_group 1;" ::: "memory");
        } else {
            asm volatile("cp.async.wait_group 0;" ::: "memory");
        }
        __syncthreads();
        uint32_t aA = base0 + (cb & 1) * STG6;
        uint32_t aB0 = aA + ABUF;
        #pragma unroll
        for (int tap = 0; tap < 9; tap++) {
            const int d = (tap / 3) * WP + (tap % 3);   // row shift within union buffer
            #pragma unroll
            for (int kk = 0; kk < 2; kk++) {
                uint32_t a[4];
                uint32_t aoff = sw64((uint32_t)((16*w + (lane & 15) + d) * 64
                                                + kk * 32 + (lane >> 4) * 16));
                ldm4(a, aA + aoff);
                #pragma unroll
                for (int p = 0; p < 4; p++) {
                    uint32_t boff = aB0 + tap*4096
                        + sw64((uint32_t)((p*16 + (lane & 15)) * 64 + kk * 32 + (lane >> 4) * 16));
                    uint32_t bb[4];
                    ldm4(bb, boff);
                    mma16816h(acc[2*p],   a, bb[0], bb[2]);
                    mma16816h(acc[2*p+1], a, bb[1], bb[3]);
                }
            }
        }
        __syncthreads();
    }

    // epilogue: frag -> smem [o][lp_local] stride 260 -> gmem (skip pads / overrun)
    float* sD = (float*)sdy;                           // 64 x 260 floats
    int r = lane >> 2, c2 = (lane & 3) * 2;
    int lbase = 16*w;
    #pragma unroll
    for (int q = 0; q < 8; q++) {
        int o = q * 8 + c2;
        sD[(o    ) * 260 + lbase + r    ] = acc[q][0];
        sD[(o + 1) * 260 + lbase + r    ] = acc[q][1];
        sD[(o    ) * 260 + lbase + r + 8] = acc[q][2];
        sD[(o + 1) * 260 + lbase + r + 8] = acc[q][3];
    }
    __syncthreads();
    float* ob = out + (size_t)b * C3 * HW;
    #pragma unroll 4
    for (int i = t; i < 16384; i += 512) {
        int o = i >> 8, ll = i & 255;
        int lp = l0 + ll;
        if (lp < LP) {
            int y = lp / WP;
            int x = lp - y * WP;
            if (x < 96)
                ob[(size_t)o * HW + y * 96 + x] = sD[o * 260 + ll];
        }
    }
}

// ---------------- launch ----------------
extern "C" void kernel_launch(void* const* d_in, const int* in_sizes, int n_in,
                              void* d_out, int out_size) {
    const float* x     = (const float*)d_in[0];
    const float* w1    = (const float*)d_in[1];
    const float* f1ce  = (const float*)d_in[2];
    const float* f1gd  = (const float*)d_in[3];
    const float* f1gd2 = (const float*)d_in[4];
    const float* f1ci  = (const float*)d_in[5];
    const float* w2    = (const float*)d_in[6];
    const float* f2ce  = (const float*)d_in[7];
    const float* f2gd  = (const float*)d_in[8];
    const float* f2gd2 = (const float*)d_in[9];
    const float* f2ci  = (const float*)d_in[10];
    float* out = (float*)d_out;

    cudaFuncSetAttribute(k6_fc2, cudaFuncAttributeMaxDynamicSharedMemorySize, 2*STG6);

    k1_gl1<<<B*C1, 256>>>(x);
    k2_dyn1<<<B, 256>>>(w1, f1ce, f1gd, f1gd2, f1ci);
    kx_t<<<dim3(HW/64, B), 256>>>(x);
    k3t<<<dim3(HW/128, 4, B), 256>>>();
    k0_zero<<<(B*576*128 + 255)/256, 256>>>();
    k4a_part<<<dim3(24, B), 256>>>();
    k4b_red<<<dim3(9, B), 256>>>();
    k5a<<<B, 256>>>(f2ce, f2gd, f2gd2, f2ci);
    k5b<<<(B*9*C3*C2)/256, 256>>>(w2);
    k6_fc2<<<dim3(37, B), 512, 2*STG6>>>(out);
}

// round 14
// speedup vs baseline: 1.8011x; 1.0424x over previous
#include <cuda_runtime.h>
#include <cuda_fp16.h>
#include <math.h>
#include <float.h>
#include <stdint.h>

#define B  4
#define C1 64
#define C2 256
#define C3 64
#define HW 9216
#define WP 98        // padded row stride (96 real + 2 zero pad)
#define LP 9408      // 96*98 padded length
#define GOFF 99      // top guard rows
#define HPAD 9792    // 99 guard + 9408 + 285 guard

// ---------------- scratch ----------------
__device__ float g_gl1[B*C1];
__device__ float g_gl2[B*C2*9];
__device__ float g_outA[B*C2*9];
__device__ float g_ocp2[B*C3*9];
__device__ float g_p4[B*3*8*3*256];                                // k4 partial maxes
__device__ __align__(16) unsigned short g_dyn1h[B*C2*C1];          // fp16 fc1 weights [b][o][c]
__device__ __align__(16) unsigned short g_hth[(size_t)B*HPAD*C2];  // fp16 h, [b][lp_row][c]
__device__ __align__(16) unsigned short g_w2h[B*9*C3*C2];          // fp16 w, [b][tap][o][c]

// ---------------- helpers ----------------
__device__ __forceinline__ uint32_t smem_u32(const void* p) {
    uint32_t a;
    asm("{ .reg .u64 t; cvta.to.shared.u64 t, %1; cvt.u32.u64 %0, t; }" : "=r"(a) : "l"(p));
    return a;
}
__device__ __forceinline__ void cp16(uint32_t dst, const void* src) {
    asm volatile("cp.async.cg.shared.global [%0], [%1], 16;" :: "r"(dst), "l"(src));
}
__device__ __forceinline__ void ldm4(uint32_t* r, uint32_t addr) {
    asm volatile("ldmatrix.sync.aligned.m8n8.x4.shared.b16 {%0,%1,%2,%3}, [%4];"
        : "=r"(r[0]), "=r"(r[1]), "=r"(r[2]), "=r"(r[3]) : "r"(addr));
}
__device__ __forceinline__ void mma16816h(float* d, const uint32_t* a, uint32_t b0, uint32_t b1) {
    asm volatile("mma.sync.aligned.m16n8k16.row.col.f32.f16.f16.f32 "
        "{%0,%1,%2,%3}, {%4,%5,%6,%7}, {%8,%9}, {%0,%1,%2,%3};"
        : "+f"(d[0]), "+f"(d[1]), "+f"(d[2]), "+f"(d[3])
        : "r"(a[0]), "r"(a[1]), "r"(a[2]), "r"(a[3]), "r"(b0), "r"(b1));
}
__device__ __forceinline__ uint32_t sw128(uint32_t off) { return off ^ ((off >> 3) & 0x70); }
__device__ __forceinline__ uint32_t sw64(uint32_t off)  { return off ^ ((off >> 3) & 0x30); }

// ---------------- K0: zero guard rows + x-pad columns of g_hth ----------------
__global__ void k0_zero() {
    int i = blockIdx.x * 256 + threadIdx.x;       // over B*576*128 u32
    if (i >= B * 576 * 128) return;
    int u = i & 127;
    int rr = (i >> 7) % 576;
    int b = i / (576 * 128);
    int row;
    if (rr < 99) row = rr;
    else if (rr < 291) {
        int k = rr - 99;
        row = GOFF + (k >> 1) * WP + 96 + (k & 1);
    } else {
        row = GOFF + LP + (rr - 291);
    }
    ((uint32_t*)g_hth)[((size_t)b * HPAD + row) * 128 + u] = 0;
}

// ---------------- K1: gl1 ----------------
__global__ void k1_gl1(const float* __restrict__ x) {
    int bc = blockIdx.x;
    const float* p = x + (size_t)bc * HW;
    float m = -FLT_MAX;
    for (int l = threadIdx.x; l < HW; l += 256) m = fmaxf(m, p[l]);
    #pragma unroll
    for (int off = 16; off; off >>= 1) m = fmaxf(m, __shfl_xor_sync(0xffffffffu, m, off));
    __shared__ float sm[8];
    if ((threadIdx.x & 31) == 0) sm[threadIdx.x >> 5] = m;
    __syncthreads();
    if (threadIdx.x == 0) {
        float r = sm[0];
        #pragma unroll
        for (int i = 1; i < 8; i++) r = fmaxf(r, sm[i]);
        g_gl1[bc] = r;
    }
}

// ---------------- K2: fc1 dynamic weights (fp16 out) ----------------
__global__ void k2_dyn1(const float* __restrict__ w1, const float* ce, const float* gd,
                        const float* gd2, const float* __restrict__ ci) {
    int b = blockIdx.x, t = threadIdx.x;
    __shared__ float s1[C1], sre[C1];
    float cev = ce[0], gdv = gd[0], gd2v = gd2[0];
    if (t < C1) {
        float r = fmaxf(g_gl1[b*C1 + t] * cev, 0.f);
        sre[t] = r; s1[t] = r * gdv;
    }
    __syncthreads();
    int p = t >> 5, o2 = t & 31;
    float v = 0.f;
    #pragma unroll
    for (int g = 0; g < 8; g++) v += sre[p*8+g] * ci[o2*8+g];
    float s2 = fmaxf(v, 0.f) * gd2v;
    for (int c = 0; c < C1; c++) {
        float s = s1[c] + s2;
        float w = w1[t*C1 + c] / (1.f + expf(-s));
        g_dyn1h[(b*C2 + t)*C1 + c] = __half_as_ushort(__float2half(w));
    }
}

// ---------------- K3X: fused fc1 (x fp32 -> fp16 mma, all 4 og) + GELU -> padded h ----------------
// smem: A fp16 128x64 sw128 [0,16K) | B fp16 256x64 sw128 [16K,48K) | pack 128x68 u16 [48K, +17408)
__global__ __launch_bounds__(256) void k3x(const float* __restrict__ x) {
    extern __shared__ __align__(128) unsigned char sdx[];
    uint32_t aA = smem_u32(sdx);
    uint32_t aB = aA + 16384;
    unsigned short* sh16 = (unsigned short*)(sdx + 49152);
    int l0 = blockIdx.x * 128, b = blockIdx.y;
    int t = threadIdx.x;

    // stage B: all 256 o-rows x 64 c via cp.async
    const unsigned short* wb = g_dyn1h + (size_t)b * C2 * 64;
    #pragma unroll
    for (int j = 0; j < 8; j++) {
        int i = t + j * 256;
        int row = i >> 3, u = i & 7;
        cp16(aB + sw128((uint32_t)(row*128 + u*16)), wb + (size_t)row*64 + u*8);
    }
    asm volatile("cp.async.commit_group;" ::: "memory");

    // stage A: direct fp32 x loads (coalesced over l), convert fp16, swizzled smem store
    const float* xb = x + (size_t)b * C1 * HW + l0;
    #pragma unroll
    for (int j = 0; j < 32; j++) {
        int idx = j * 256 + t;
        int c = idx >> 7, l = idx & 127;
        float v = xb[(size_t)c * HW + l];
        uint32_t so = sw128((uint32_t)(l*128 + c*2));
        *(unsigned short*)(sdx + so) = __half_as_ushort(__float2half(v));
    }
    asm volatile("cp.async.wait_group 0;" ::: "memory");
    __syncthreads();

    int w = t >> 5, lane = t & 31;
    // A fragments once (shared across all og)
    uint32_t a[4][4];
    #pragma unroll
    for (int kk = 0; kk < 4; kk++) {
        uint32_t aoff = sw128((uint32_t)((16*w + (lane & 15)) * 128 + kk * 32 + (lane >> 4) * 16));
        ldm4(a[kk], aA + aoff);
    }

    int r = lane >> 2, c2 = (lane & 3) * 2;
    #pragma unroll 1
    for (int og = 0; og < 4; og++) {
        float acc[8][4];
        #pragma unroll
        for (int i = 0; i < 8; i++)
            #pragma unroll
            for (int j = 0; j < 4; j++) acc[i][j] = 0.f;
        #pragma unroll
        for (int kk = 0; kk < 4; kk++) {
            #pragma unroll
            for (int p = 0; p < 4; p++) {
                uint32_t boff = sw128((uint32_t)((og*64 + p*16 + (lane & 15)) * 128
                                                 + kk * 32 + (lane >> 4) * 16));
                uint32_t bb[4];
                ldm4(bb, aB + boff);
                mma16816h(acc[2*p],   a[kk], bb[0], bb[2]);
                mma16816h(acc[2*p+1], a[kk], bb[1], bb[3]);
            }
        }
        // pack: GELU + fp16, [l][o_local] stride 68
        #pragma unroll
        for (int p = 0; p < 4; p++)
            #pragma unroll
            for (int q = 0; q < 2; q++) {
                int n = p*16 + q*8 + c2;
                #pragma unroll
                for (int hv = 0; hv < 2; hv++) {
                    int m = 16*w + r + hv*8;
                    #pragma unroll
                    for (int e = 0; e < 2; e++) {
                        float v = acc[2*p+q][hv*2 + e];
                        v = 0.5f * v * (1.f + erff(v * 0.70710678118654752f));
                        sh16[m*68 + n + e] = __half_as_ushort(__float2half(v));
                    }
                }
            }
        __syncthreads();
        #pragma unroll
        for (int i = t; i < 2048; i += 256) {
            int row = i >> 4, q = i & 15;
            uint2 vh = *(const uint2*)&sh16[row*68 + q*4];
            int l = l0 + row;
            int y = l / 96;
            int lp = y * WP + (l - y * 96);
            ((uint2*)g_hth)[((size_t)b*HPAD + GOFF + lp)*64 + og*16 + q] = vh;
        }
        __syncthreads();
    }
}

// ---------------- K4a: partial 3x3 adaptive max over fp16 h (stride WP) ----------------
__global__ void k4a_part() {
    int bx = blockIdx.x;                 // 24 = ybin(3) * ys(8)
    int b = blockIdx.y;
    int ybin = bx >> 3, ys = bx & 7;
    int y0 = ybin * 32 + ys * 4;
    int t = threadIdx.x;                 // c
    const unsigned short* base = g_hth + ((size_t)b * HPAD + GOFF) * 256 + t;
    float m[3] = {-FLT_MAX, -FLT_MAX, -FLT_MAX};
    #pragma unroll
    for (int yy = 0; yy < 4; yy++) {
        const unsigned short* rp = base + (size_t)(y0 + yy) * WP * 256;
        #pragma unroll
        for (int xb = 0; xb < 3; xb++) {
            float mm = m[xb];
            #pragma unroll 8
            for (int xx = 0; xx < 32; xx++)
                mm = fmaxf(mm, __half2float(__ushort_as_half(rp[(size_t)(xb*32 + xx) * 256])));
            m[xb] = mm;
        }
    }
    #pragma unroll
    for (int xb = 0; xb < 3; xb++)
        g_p4[((((size_t)b*3 + ybin)*8 + ys)*3 + xb)*256 + t] = m[xb];
}

// ---------------- K4b: reduce partials -> gl2 ----------------
__global__ void k4b_red() {
    int bin = blockIdx.x;                // ybin*3 + xbin
    int b = blockIdx.y;
    int t = threadIdx.x;
    int ybin = bin / 3, xbin = bin % 3;
    float m = -FLT_MAX;
    #pragma unroll
    for (int ys = 0; ys < 8; ys++)
        m = fmaxf(m, g_p4[((((size_t)b*3 + ybin)*8 + ys)*3 + xbin)*256 + t]);
    g_gl2[(b*C2 + t)*9 + ybin*3 + xbin] = m;
}

// ---------------- K5a: fc2 gating scalars ----------------
__global__ void k5a(const float* __restrict__ ce_w, const float* __restrict__ gd_w,
                    const float* __restrict__ gd2_w, const float* __restrict__ ci_w) {
    int b = blockIdx.x, t = threadIdx.x;
    __shared__ float sre[C2][5];
    {
        float glv[9];
        #pragma unroll
        for (int k = 0; k < 9; k++) glv[k] = g_gl2[(b*C2 + t)*9 + k];
        float rc[5];
        #pragma unroll
        for (int n = 0; n < 5; n++) {
            float v = 0.f;
            #pragma unroll
            for (int k = 0; k < 9; k++) v += glv[k] * ce_w[n*9 + k];
            rc[n] = fmaxf(v, 0.f);
            sre[t][n] = rc[n];
        }
        #pragma unroll
        for (int k = 0; k < 9; k++) {
            float v = 0.f;
            #pragma unroll
            for (int n = 0; n < 5; n++) v += rc[n] * gd_w[k*5 + n];
            g_outA[(b*C2 + t)*9 + k] = v;
        }
    }
    __syncthreads();
    if (t < C3) {
        int p = t >> 1, o2 = t & 1;
        float v[5];
        #pragma unroll
        for (int n = 0; n < 5; n++) {
            float s = 0.f;
            #pragma unroll
            for (int g = 0; g < 8; g++) s += sre[p*8+g][n] * ci_w[o2*8 + g];
            v[n] = fmaxf(s, 0.f);
        }
        #pragma unroll
        for (int k = 0; k < 9; k++) {
            float s = 0.f;
            #pragma unroll
            for (int n = 0; n < 5; n++) s += v[n] * gd2_w[k*5 + n];
            g_ocp2[(b*C3 + t)*9 + k] = s;
        }
    }
}

// ---------------- K5b: fp16 dynamic fc2 weights, [b][tap][o][c] ----------------
__global__ void k5b(const float* __restrict__ w2) {
    int idx = blockIdx.x * 256 + threadIdx.x;       // ((b*9+k)*64+o)*256 + c
    int c = idx & 255;
    int o = (idx >> 8) & 63;
    int t2 = idx >> 14;
    int k = t2 % 9, b = t2 / 9;
    float s = g_outA[(b*C2 + c)*9 + k] + g_ocp2[(b*C3 + o)*9 + k];
    float w = w2[(o*C2 + c)*9 + k] / (1.f + expf(-s));
    g_w2h[idx] = __half_as_ushort(__float2half(w));
}

// ---------------- K6: fc2 fp16 mma; padded-stride shifts (exact), 37 tiles x B = 1 wave ----------------
#define ABUF 29056                         // 454 rows x 64B (c=32)
#define BBUF 36864                         // 9 taps x 64 o x 64B
#define STG6 (ABUF + BBUF)                 // 65920 per stage, x2 = 131840
__device__ __forceinline__ void stage6(uint32_t base, const unsigned short* hh,
        int b, int l0, int cb, int t) {
    const unsigned short* ha = hh + (size_t)(l0 - GOFF) * 256 + cb * 32;
    #pragma unroll
    for (int j = 0; j < 4; j++) {
        int i = t + j * 512;
        if (i < 1816) {                    // 454 rows x 4 chunks
            int row = i >> 2, u = i & 3;
            cp16(base + sw64((uint32_t)(row*64 + u*16)), ha + (size_t)row*256 + u*8);
        }
    }
    const unsigned short* wb = g_w2h + (size_t)b * 9 * 64 * 256 + cb * 32;
    #pragma unroll
    for (int j = 0; j < 5; j++) {
        int i = t + j * 512;                       // 0..2303
        if (i < 2304) {
            int row2 = i >> 2, u = i & 3;          // row2 = tap*64 + o
            int tap = row2 >> 6, o = row2 & 63;
            cp16(base + ABUF + tap*4096 + sw64((uint32_t)(o*64 + u*16)),
                 wb + (size_t)row2 * 256 + u*8);
        }
    }
}

__global__ __launch_bounds__(512, 1) void k6_fc2(float* __restrict__ out) {
    extern __shared__ __align__(128) unsigned char sdy[];
    uint32_t base0 = smem_u32(sdy);
    int tile = blockIdx.x, b = blockIdx.y;
    int l0 = tile * 256, t = threadIdx.x;
    int w = t >> 5, lane = t & 31;       // 16 warps, warp owns m16

    const unsigned short* hh = g_hth + ((size_t)b * HPAD + GOFF) * 256;

    float acc[8][4];
    #pragma unroll
    for (int i = 0; i < 8; i++)
        #pragma unroll
        for (int j = 0; j < 4; j++) acc[i][j] = 0.f;

    stage6(base0, hh, b, l0, 0, t);
    asm volatile("cp.async.commit_group;" ::: "memory");

    for (int cb = 0; cb < 8; cb++) {
        if (cb < 7) {
            stage6(base0 + ((cb + 1) & 1) * STG6, hh, b, l0, cb + 1, t);
            asm volatile("cp.async.commit_group;" ::: "memory");
            asm volatile("cp.async.wait_group 1;" ::: "memory");
        } else {
            asm volatile("cp.async.wait_group 0;" ::: "memory");
        }
        __syncthreads();
        uint32_t aA = base0 + (cb & 1) * STG6;
        uint32_t aB0 = aA + ABUF;
        #pragma unroll
        for (int tap = 0; tap < 9; tap++) {
            const int d = (tap / 3) * WP + (tap % 3);
            #pragma unroll
            for (int kk = 0; kk < 2; kk++) {
                uint32_t a[4];
                uint32_t aoff = sw64((uint32_t)((16*w + (lane & 15) + d) * 64
                                                + kk * 32 + (lane >> 4) * 16));
                ldm4(a, aA + aoff);
                #pragma unroll
                for (int p = 0; p < 4; p++) {
                    uint32_t boff = aB0 + tap*4096
                        + sw64((uint32_t)((p*16 + (lane & 15)) * 64 + kk * 32 + (lane >> 4) * 16));
                    uint32_t bb[4];
                    ldm4(bb, boff);
                    mma16816h(acc[2*p],   a, bb[0], bb[2]);
                    mma16816h(acc[2*p+1], a, bb[1], bb[3]);
                }
            }
        }
        __syncthreads();
    }

    // epilogue: frag -> smem [o][lp_local] stride 260 -> gmem (skip pads / overrun)
    float* sD = (float*)sdy;
    int r = lane >> 2, c2 = (lane & 3) * 2;
    int lbase = 16*w;
    #pragma unroll
    for (int q = 0; q < 8; q++) {
        int o = q * 8 + c2;
        sD[(o    ) * 260 + lbase + r    ] = acc[q][0];
        sD[(o + 1) * 260 + lbase + r    ] = acc[q][1];
        sD[(o    ) * 260 + lbase + r + 8] = acc[q][2];
        sD[(o + 1) * 260 + lbase + r + 8] = acc[q][3];
    }
    __syncthreads();
    float* ob = out + (size_t)b * C3 * HW;
    #pragma unroll 4
    for (int i = t; i < 16384; i += 512) {
        int o = i >> 8, ll = i & 255;
        int lp = l0 + ll;
        if (lp < LP) {
            int y = lp / WP;
            int x = lp - y * WP;
            if (x < 96)
                ob[(size_t)o * HW + y * 96 + x] = sD[o * 260 + ll];
        }
    }
}

// ---------------- launch ----------------
extern "C" void kernel_launch(void* const* d_in, const int* in_sizes, int n_in,
                              void* d_out, int out_size) {
    const float* x     = (const float*)d_in[0];
    const float* w1    = (const float*)d_in[1];
    const float* f1ce  = (const float*)d_in[2];
    const float* f1gd  = (const float*)d_in[3];
    const float* f1gd2 = (const float*)d_in[4];
    const float* f1ci  = (const float*)d_in[5];
    const float* w2    = (const float*)d_in[6];
    const float* f2ce  = (const float*)d_in[7];
    const float* f2gd  = (const float*)d_in[8];
    const float* f2gd2 = (const float*)d_in[9];
    const float* f2ci  = (const float*)d_in[10];
    float* out = (float*)d_out;

    cudaFuncSetAttribute(k6_fc2, cudaFuncAttributeMaxDynamicSharedMemorySize, 2*STG6);
    cudaFuncSetAttribute(k3x, cudaFuncAttributeMaxDynamicSharedMemorySize, 66560);

    k1_gl1<<<B*C1, 256>>>(x);
    k2_dyn1<<<B, 256>>>(w1, f1ce, f1gd, f1gd2, f1ci);
    k3x<<<dim3(HW/128, B), 256, 66560>>>(x);
    k0_zero<<<(B*576*128 + 255)/256, 256>>>();
    k4a_part<<<dim3(24, B), 256>>>();
    k4b_red<<<dim3(9, B), 256>>>();
    k5a<<<B, 256>>>(f2ce, f2gd, f2gd2, f2ci);
    k5b<<<(B*9*C3*C2)/256, 256>>>(w2);
    k6_fc2<<<dim3(37, B), 512, 2*STG6>>>(out);
}

// round 15
// speedup vs baseline: 1.8077x; 1.0037x over previous
#include <cuda_runtime.h>
#include <cuda_fp16.h>
#include <math.h>
#include <float.h>
#include <stdint.h>

#define B  4
#define C1 64
#define C2 256
#define C3 64
#define HW 9216
#define WP 98        // padded row stride (96 real + 2 zero pad)
#define LP 9408      // 96*98 padded length
#define GOFF 99      // top guard rows
#define HPAD 9792    // 99 guard + 9408 + 285 guard

// ---------------- scratch ----------------
__device__ float g_gl1[B*C1];
__device__ float g_outA[B*C2*9];
__device__ float g_ocp2[B*C3*9];
__device__ float g_p4[B*3*8*3*256];                                // k4 partial maxes
__device__ __align__(16) unsigned short g_dyn1h[B*C2*C1];          // fp16 fc1 weights [b][o][c]
__device__ __align__(16) unsigned short g_hth[(size_t)B*HPAD*C2];  // fp16 h, [b][lp_row][c]
__device__ __align__(16) unsigned short g_w2h[B*9*C3*C2];          // fp16 w, [b][tap][o][c]

// ---------------- helpers ----------------
__device__ __forceinline__ uint32_t smem_u32(const void* p) {
    uint32_t a;
    asm("{ .reg .u64 t; cvta.to.shared.u64 t, %1; cvt.u32.u64 %0, t; }" : "=r"(a) : "l"(p));
    return a;
}
__device__ __forceinline__ void cp16(uint32_t dst, const void* src) {
    asm volatile("cp.async.cg.shared.global [%0], [%1], 16;" :: "r"(dst), "l"(src));
}
__device__ __forceinline__ void ldm4(uint32_t* r, uint32_t addr) {
    asm volatile("ldmatrix.sync.aligned.m8n8.x4.shared.b16 {%0,%1,%2,%3}, [%4];"
        : "=r"(r[0]), "=r"(r[1]), "=r"(r[2]), "=r"(r[3]) : "r"(addr));
}
__device__ __forceinline__ void mma16816h(float* d, const uint32_t* a, uint32_t b0, uint32_t b1) {
    asm volatile("mma.sync.aligned.m16n8k16.row.col.f32.f16.f16.f32 "
        "{%0,%1,%2,%3}, {%4,%5,%6,%7}, {%8,%9}, {%0,%1,%2,%3};"
        : "+f"(d[0]), "+f"(d[1]), "+f"(d[2]), "+f"(d[3])
        : "r"(a[0]), "r"(a[1]), "r"(a[2]), "r"(a[3]), "r"(b0), "r"(b1));
}
__device__ __forceinline__ uint32_t sw128(uint32_t off) { return off ^ ((off >> 3) & 0x70); }
__device__ __forceinline__ uint32_t sw64(uint32_t off)  { return off ^ ((off >> 3) & 0x30); }

// ---------------- K0: zero guard rows + x-pad columns (uint4) ----------------
__global__ void k0_zero() {
    int i = blockIdx.x * 256 + threadIdx.x;       // over B*576*32 uint4
    if (i >= B * 576 * 32) return;
    int u = i & 31;
    int rr = (i >> 5) % 576;
    int b = i / (576 * 32);
    int row;
    if (rr < 99) row = rr;
    else if (rr < 291) {
        int k = rr - 99;
        row = GOFF + (k >> 1) * WP + 96 + (k & 1);
    } else {
        row = GOFF + LP + (rr - 291);
    }
    ((uint4*)g_hth)[((size_t)b * HPAD + row) * 32 + u] = make_uint4(0, 0, 0, 0);
}

// ---------------- K1: gl1 ----------------
__global__ void k1_gl1(const float* __restrict__ x) {
    int bc = blockIdx.x;
    const float* p = x + (size_t)bc * HW;
    float m = -FLT_MAX;
    for (int l = threadIdx.x; l < HW; l += 256) m = fmaxf(m, p[l]);
    #pragma unroll
    for (int off = 16; off; off >>= 1) m = fmaxf(m, __shfl_xor_sync(0xffffffffu, m, off));
    __shared__ float sm[8];
    if ((threadIdx.x & 31) == 0) sm[threadIdx.x >> 5] = m;
    __syncthreads();
    if (threadIdx.x == 0) {
        float r = sm[0];
        #pragma unroll
        for (int i = 1; i < 8; i++) r = fmaxf(r, sm[i]);
        g_gl1[bc] = r;
    }
}

// ---------------- K2: fc1 dynamic weights (fp16 out) ----------------
__global__ void k2_dyn1(const float* __restrict__ w1, const float* ce, const float* gd,
                        const float* gd2, const float* __restrict__ ci) {
    int b = blockIdx.x, t = threadIdx.x;
    __shared__ float s1[C1], sre[C1];
    float cev = ce[0], gdv = gd[0], gd2v = gd2[0];
    if (t < C1) {
        float r = fmaxf(g_gl1[b*C1 + t] * cev, 0.f);
        sre[t] = r; s1[t] = r * gdv;
    }
    __syncthreads();
    int p = t >> 5, o2 = t & 31;
    float v = 0.f;
    #pragma unroll
    for (int g = 0; g < 8; g++) v += sre[p*8+g] * ci[o2*8+g];
    float s2 = fmaxf(v, 0.f) * gd2v;
    for (int c = 0; c < C1; c++) {
        float s = s1[c] + s2;
        float w = w1[t*C1 + c] / (1.f + expf(-s));
        g_dyn1h[(b*C2 + t)*C1 + c] = __half_as_ushort(__float2half(w));
    }
}

// ---------------- K3X: fused fc1 (x fp32 -> fp16 mma, all 4 og) + GELU -> padded h ----------------
__global__ __launch_bounds__(256) void k3x(const float* __restrict__ x) {
    extern __shared__ __align__(128) unsigned char sdx[];
    uint32_t aA = smem_u32(sdx);
    uint32_t aB = aA + 16384;
    unsigned short* sh16 = (unsigned short*)(sdx + 49152);
    int l0 = blockIdx.x * 128, b = blockIdx.y;
    int t = threadIdx.x;

    const unsigned short* wb = g_dyn1h + (size_t)b * C2 * 64;
    #pragma unroll
    for (int j = 0; j < 8; j++) {
        int i = t + j * 256;
        int row = i >> 3, u = i & 7;
        cp16(aB + sw128((uint32_t)(row*128 + u*16)), wb + (size_t)row*64 + u*8);
    }
    asm volatile("cp.async.commit_group;" ::: "memory");

    const float* xb = x + (size_t)b * C1 * HW + l0;
    #pragma unroll
    for (int j = 0; j < 32; j++) {
        int idx = j * 256 + t;
        int c = idx >> 7, l = idx & 127;
        float v = xb[(size_t)c * HW + l];
        uint32_t so = sw128((uint32_t)(l*128 + c*2));
        *(unsigned short*)(sdx + so) = __half_as_ushort(__float2half(v));
    }
    asm volatile("cp.async.wait_group 0;" ::: "memory");
    __syncthreads();

    int w = t >> 5, lane = t & 31;
    uint32_t a[4][4];
    #pragma unroll
    for (int kk = 0; kk < 4; kk++) {
        uint32_t aoff = sw128((uint32_t)((16*w + (lane & 15)) * 128 + kk * 32 + (lane >> 4) * 16));
        ldm4(a[kk], aA + aoff);
    }

    int r = lane >> 2, c2 = (lane & 3) * 2;
    #pragma unroll 1
    for (int og = 0; og < 4; og++) {
        float acc[8][4];
        #pragma unroll
        for (int i = 0; i < 8; i++)
            #pragma unroll
            for (int j = 0; j < 4; j++) acc[i][j] = 0.f;
        #pragma unroll
        for (int kk = 0; kk < 4; kk++) {
            #pragma unroll
            for (int p = 0; p < 4; p++) {
                uint32_t boff = sw128((uint32_t)((og*64 + p*16 + (lane & 15)) * 128
                                                 + kk * 32 + (lane >> 4) * 16));
                uint32_t bb[4];
                ldm4(bb, aB + boff);
                mma16816h(acc[2*p],   a[kk], bb[0], bb[2]);
                mma16816h(acc[2*p+1], a[kk], bb[1], bb[3]);
            }
        }
        #pragma unroll
        for (int p = 0; p < 4; p++)
            #pragma unroll
            for (int q = 0; q < 2; q++) {
                int n = p*16 + q*8 + c2;
                #pragma unroll
                for (int hv = 0; hv < 2; hv++) {
                    int m = 16*w + r + hv*8;
                    #pragma unroll
                    for (int e = 0; e < 2; e++) {
                        float v = acc[2*p+q][hv*2 + e];
                        v = 0.5f * v * (1.f + erff(v * 0.70710678118654752f));
                        sh16[m*68 + n + e] = __half_as_ushort(__float2half(v));
                    }
                }
            }
        __syncthreads();
        #pragma unroll
        for (int i = t; i < 2048; i += 256) {
            int row = i >> 4, q = i & 15;
            uint2 vh = *(const uint2*)&sh16[row*68 + q*4];
            int l = l0 + row;
            int y = l / 96;
            int lp = y * WP + (l - y * 96);
            ((uint2*)g_hth)[((size_t)b*HPAD + GOFF + lp)*64 + og*16 + q] = vh;
        }
        __syncthreads();
    }
}

// ---------------- K4a: partial 3x3 adaptive max over fp16 h (stride WP) ----------------
__global__ void k4a_part() {
    int bx = blockIdx.x;                 // 24 = ybin(3) * ys(8)
    int b = blockIdx.y;
    int ybin = bx >> 3, ys = bx & 7;
    int y0 = ybin * 32 + ys * 4;
    int t = threadIdx.x;                 // c
    const unsigned short* base = g_hth + ((size_t)b * HPAD + GOFF) * 256 + t;
    float m[3] = {-FLT_MAX, -FLT_MAX, -FLT_MAX};
    #pragma unroll
    for (int yy = 0; yy < 4; yy++) {
        const unsigned short* rp = base + (size_t)(y0 + yy) * WP * 256;
        #pragma unroll
        for (int xb = 0; xb < 3; xb++) {
            float mm = m[xb];
            #pragma unroll 8
            for (int xx = 0; xx < 32; xx++)
                mm = fmaxf(mm, __half2float(__ushort_as_half(rp[(size_t)(xb*32 + xx) * 256])));
            m[xb] = mm;
        }
    }
    #pragma unroll
    for (int xb = 0; xb < 3; xb++)
        g_p4[((((size_t)b*3 + ybin)*8 + ys)*3 + xb)*256 + t] = m[xb];
}

// ---------------- K45: fused partial-reduce + fc2 gating scalars ----------------
__global__ void k45(const float* __restrict__ ce_w, const float* __restrict__ gd_w,
                    const float* __restrict__ gd2_w, const float* __restrict__ ci_w) {
    int b = blockIdx.x, t = threadIdx.x;           // t = c (256)
    __shared__ float sre[C2][5];
    // reduce partials -> glv[9] in registers
    float glv[9];
    #pragma unroll
    for (int ybin = 0; ybin < 3; ybin++)
        #pragma unroll
        for (int xbin = 0; xbin < 3; xbin++) {
            float m = -FLT_MAX;
            #pragma unroll
            for (int ys = 0; ys < 8; ys++)
                m = fmaxf(m, g_p4[((((size_t)b*3 + ybin)*8 + ys)*3 + xbin)*256 + t]);
            glv[ybin*3 + xbin] = m;
        }
    {
        float rc[5];
        #pragma unroll
        for (int n = 0; n < 5; n++) {
            float v = 0.f;
            #pragma unroll
            for (int k = 0; k < 9; k++) v += glv[k] * ce_w[n*9 + k];
            rc[n] = fmaxf(v, 0.f);
            sre[t][n] = rc[n];
        }
        #pragma unroll
        for (int k = 0; k < 9; k++) {
            float v = 0.f;
            #pragma unroll
            for (int n = 0; n < 5; n++) v += rc[n] * gd_w[k*5 + n];
            g_outA[(b*C2 + t)*9 + k] = v;
        }
    }
    __syncthreads();
    if (t < C3) {
        int p = t >> 1, o2 = t & 1;
        float v[5];
        #pragma unroll
        for (int n = 0; n < 5; n++) {
            float s = 0.f;
            #pragma unroll
            for (int g = 0; g < 8; g++) s += sre[p*8+g][n] * ci_w[o2*8 + g];
            v[n] = fmaxf(s, 0.f);
        }
        #pragma unroll
        for (int k = 0; k < 9; k++) {
            float s = 0.f;
            #pragma unroll
            for (int n = 0; n < 5; n++) s += v[n] * gd2_w[k*5 + n];
            g_ocp2[(b*C3 + t)*9 + k] = s;
        }
    }
}

// ---------------- K5b: fp16 dynamic fc2 weights, [b][tap][o][c] ----------------
__global__ void k5b(const float* __restrict__ w2) {
    int idx = blockIdx.x * 256 + threadIdx.x;       // ((b*9+k)*64+o)*256 + c
    int c = idx & 255;
    int o = (idx >> 8) & 63;
    int t2 = idx >> 14;
    int k = t2 % 9, b = t2 / 9;
    float s = g_outA[(b*C2 + c)*9 + k] + g_ocp2[(b*C3 + o)*9 + k];
    float w = w2[(o*C2 + c)*9 + k] / (1.f + expf(-s));
    g_w2h[idx] = __half_as_ushort(__float2half(w));
}

// ---------------- K6: fc2 fp16 mma; padded-stride shifts (exact), 37 tiles x B = 1 wave ----------------
#define ABUF 29056                         // 454 rows x 64B (c=32)
#define BBUF 36864                         // 9 taps x 64 o x 64B
#define STG6 (ABUF + BBUF)                 // 65920 per stage, x2 = 131840
__device__ __forceinline__ void stage6(uint32_t base, const unsigned short* hh,
        int b, int l0, int cb, int t) {
    const unsigned short* ha = hh + (size_t)(l0 - GOFF) * 256 + cb * 32;
    #pragma unroll
    for (int j = 0; j < 4; j++) {
        int i = t + j * 512;
        if (i < 1816) {
            int row = i >> 2, u = i & 3;
            cp16(base + sw64((uint32_t)(row*64 + u*16)), ha + (size_t)row*256 + u*8);
        }
    }
    const unsigned short* wb = g_w2h + (size_t)b * 9 * 64 * 256 + cb * 32;
    #pragma unroll
    for (int j = 0; j < 5; j++) {
        int i = t + j * 512;
        if (i < 2304) {
            int row2 = i >> 2, u = i & 3;
            int tap = row2 >> 6, o = row2 & 63;
            cp16(base + ABUF + tap*4096 + sw64((uint32_t)(o*64 + u*16)),
                 wb + (size_t)row2 * 256 + u*8);
        }
    }
}

__global__ __launch_bounds__(512, 1) void k6_fc2(float* __restrict__ out) {
    extern __shared__ __align__(128) unsigned char sdy[];
    uint32_t base0 = smem_u32(sdy);
    int tile = blockIdx.x, b = blockIdx.y;
    int l0 = tile * 256, t = threadIdx.x;
    int w = t >> 5, lane = t & 31;

    const unsigned short* hh = g_hth + ((size_t)b * HPAD + GOFF) * 256;

    float acc[8][4];
    #pragma unroll
    for (int i = 0; i < 8; i++)
        #pragma unroll
        for (int j = 0; j < 4; j++) acc[i][j] = 0.f;

    stage6(base0, hh, b, l0, 0, t);
    asm volatile("cp.async.commit_group;" ::: "memory");

    for (int cb = 0; cb < 8; cb++) {
        if (cb < 7) {
            stage6(base0 + ((cb + 1) & 1) * STG6, hh, b, l0, cb + 1, t);
            asm volatile("cp.async.commit_group;" ::: "memory");
            asm volatile("cp.async.wait_group 1;" ::: "memory");
        } else {
            asm volatile("cp.async.wait_group 0;" ::: "memory");
        }
        __syncthreads();
        uint32_t aA = base0 + (cb & 1) * STG6;
        uint32_t aB0 = aA + ABUF;
        #pragma unroll
        for (int tap = 0; tap < 9; tap++) {
            const int d = (tap / 3) * WP + (tap % 3);
            #pragma unroll
            for (int kk = 0; kk < 2; kk++) {
                uint32_t a[4];
                uint32_t aoff = sw64((uint32_t)((16*w + (lane & 15) + d) * 64
                                                + kk * 32 + (lane >> 4) * 16));
                ldm4(a, aA + aoff);
                #pragma unroll
                for (int p = 0; p < 4; p++) {
                    uint32_t boff = aB0 + tap*4096
                        + sw64((uint32_t)((p*16 + (lane & 15)) * 64 + kk * 32 + (lane >> 4) * 16));
                    uint32_t bb[4];
                    ldm4(bb, boff);
                    mma16816h(acc[2*p],   a, bb[0], bb[2]);
                    mma16816h(acc[2*p+1], a, bb[1], bb[3]);
                }
            }
        }
        __syncthreads();
    }

    float* sD = (float*)sdy;
    int r = lane >> 2, c2 = (lane & 3) * 2;
    int lbase = 16*w;
    #pragma unroll
    for (int q = 0; q < 8; q++) {
        int o = q * 8 + c2;
        sD[(o    ) * 260 + lbase + r    ] = acc[q][0];
        sD[(o + 1) * 260 + lbase + r    ] = acc[q][1];
        sD[(o    ) * 260 + lbase + r + 8] = acc[q][2];
        sD[(o + 1) * 260 + lbase + r + 8] = acc[q][3];
    }
    __syncthreads();
    float* ob = out + (size_t)b * C3 * HW;
    #pragma unroll 4
    for (int i = t; i < 16384; i += 512) {
        int o = i >> 8, ll = i & 255;
        int lp = l0 + ll;
        if (lp < LP) {
            int y = lp / WP;
            int x = lp - y * WP;
            if (x < 96)
                ob[(size_t)o * HW + y * 96 + x] = sD[o * 260 + ll];
        }
    }
}

// ---------------- launch ----------------
extern "C" void kernel_launch(void* const* d_in, const int* in_sizes, int n_in,
                              void* d_out, int out_size) {
    const float* x     = (const float*)d_in[0];
    const float* w1    = (const float*)d_in[1];
    const float* f1ce  = (const float*)d_in[2];
    const float* f1gd  = (const float*)d_in[3];
    const float* f1gd2 = (const float*)d_in[4];
    const float* f1ci  = (const float*)d_in[5];
    const float* w2    = (const float*)d_in[6];
    const float* f2ce  = (const float*)d_in[7];
    const float* f2gd  = (const float*)d_in[8];
    const float* f2gd2 = (const float*)d_in[9];
    const float* f2ci  = (const float*)d_in[10];
    float* out = (float*)d_out;

    cudaFuncSetAttribute(k6_fc2, cudaFuncAttributeMaxDynamicSharedMemorySize, 2*STG6);
    cudaFuncSetAttribute(k3x, cudaFuncAttributeMaxDynamicSharedMemorySize, 66560);

    k0_zero<<<(B*576*32 + 255)/256, 256>>>();
    k1_gl1<<<B*C1, 256>>>(x);
    k2_dyn1<<<B, 256>>>(w1, f1ce, f1gd, f1gd2, f1ci);
    k3x<<<dim3(HW/128, B), 256, 66560>>>(x);
    k4a_part<<<dim3(24, B), 256>>>();
    k45<<<B, 256>>>(f2ce, f2gd, f2gd2, f2ci);
    k5b<<<(B*9*C3*C2)/256, 256>>>(w2);
    k6_fc2<<<dim3(37, B), 512, 2*STG6>>>(out);
}

// round 16
// speedup vs baseline: 1.8389x; 1.0172x over previous
#include <cuda_runtime.h>
#include <cuda_fp16.h>
#include <math.h>
#include <float.h>
#include <stdint.h>

#define B  4
#define C1 64
#define C2 256
#define C3 64
#define HW 9216
#define WP 98        // padded row stride (96 real + 2 zero pad)
#define LP 9408      // 96*98 padded length
#define GOFF 99      // top guard rows
#define HPAD 9792    // 99 guard + 9408 + 285 guard

// ---------------- scratch ----------------
__device__ float g_gl1[B*C1];
__device__ float g_outA[B*C2*9];
__device__ float g_ocp2[B*C3*9];
__device__ float g_p4[B*3*8*3*256];                                // k4 partial maxes
__device__ __align__(16) unsigned short g_dyn1h[B*C2*C1];          // fp16 fc1 weights [b][o][c]
__device__ __align__(16) unsigned short g_hth[(size_t)B*HPAD*C2];  // fp16 h, [b][lp_row][c]
__device__ __align__(16) unsigned short g_w2h[B*9*C3*C2];          // fp16 w, [b][tap][o][c]

// ---------------- helpers ----------------
__device__ __forceinline__ uint32_t smem_u32(const void* p) {
    uint32_t a;
    asm("{ .reg .u64 t; cvta.to.shared.u64 t, %1; cvt.u32.u64 %0, t; }" : "=r"(a) : "l"(p));
    return a;
}
__device__ __forceinline__ void cp16(uint32_t dst, const void* src) {
    asm volatile("cp.async.cg.shared.global [%0], [%1], 16;" :: "r"(dst), "l"(src));
}
__device__ __forceinline__ void ldm4(uint32_t* r, uint32_t addr) {
    asm volatile("ldmatrix.sync.aligned.m8n8.x4.shared.b16 {%0,%1,%2,%3}, [%4];"
        : "=r"(r[0]), "=r"(r[1]), "=r"(r[2]), "=r"(r[3]) : "r"(addr));
}
__device__ __forceinline__ void mma16816h(float* d, const uint32_t* a, uint32_t b0, uint32_t b1) {
    asm volatile("mma.sync.aligned.m16n8k16.row.col.f32.f16.f16.f32 "
        "{%0,%1,%2,%3}, {%4,%5,%6,%7}, {%8,%9}, {%0,%1,%2,%3};"
        : "+f"(d[0]), "+f"(d[1]), "+f"(d[2]), "+f"(d[3])
        : "r"(a[0]), "r"(a[1]), "r"(a[2]), "r"(a[3]), "r"(b0), "r"(b1));
}
__device__ __forceinline__ uint32_t sw128(uint32_t off) { return off ^ ((off >> 3) & 0x70); }
__device__ __forceinline__ uint32_t sw64(uint32_t off)  { return off ^ ((off >> 3) & 0x30); }
__device__ __forceinline__ float gelu_f(float v) {
    return 0.5f * v * (1.f + erff(v * 0.70710678118654752f));
}

// ---------------- K0: zero guard rows + x-pad columns (uint4) ----------------
__global__ void k0_zero() {
    int i = blockIdx.x * 256 + threadIdx.x;       // over B*576*32 uint4
    if (i >= B * 576 * 32) return;
    int u = i & 31;
    int rr = (i >> 5) % 576;
    int b = i / (576 * 32);
    int row;
    if (rr < 99) row = rr;
    else if (rr < 291) {
        int k = rr - 99;
        row = GOFF + (k >> 1) * WP + 96 + (k & 1);
    } else {
        row = GOFF + LP + (rr - 291);
    }
    ((uint4*)g_hth)[((size_t)b * HPAD + row) * 32 + u] = make_uint4(0, 0, 0, 0);
}

// ---------------- K1: gl1 ----------------
__global__ void k1_gl1(const float* __restrict__ x) {
    int bc = blockIdx.x;
    const float* p = x + (size_t)bc * HW;
    float m = -FLT_MAX;
    for (int l = threadIdx.x; l < HW; l += 256) m = fmaxf(m, p[l]);
    #pragma unroll
    for (int off = 16; off; off >>= 1) m = fmaxf(m, __shfl_xor_sync(0xffffffffu, m, off));
    __shared__ float sm[8];
    if ((threadIdx.x & 31) == 0) sm[threadIdx.x >> 5] = m;
    __syncthreads();
    if (threadIdx.x == 0) {
        float r = sm[0];
        #pragma unroll
        for (int i = 1; i < 8; i++) r = fmaxf(r, sm[i]);
        g_gl1[bc] = r;
    }
}

// ---------------- K2: fc1 dynamic weights (fp16 out) ----------------
__global__ void k2_dyn1(const float* __restrict__ w1, const float* ce, const float* gd,
                        const float* gd2, const float* __restrict__ ci) {
    int b = blockIdx.x, t = threadIdx.x;
    __shared__ float s1[C1], sre[C1];
    float cev = ce[0], gdv = gd[0], gd2v = gd2[0];
    if (t < C1) {
        float r = fmaxf(g_gl1[b*C1 + t] * cev, 0.f);
        sre[t] = r; s1[t] = r * gdv;
    }
    __syncthreads();
    int p = t >> 5, o2 = t & 31;
    float v = 0.f;
    #pragma unroll
    for (int g = 0; g < 8; g++) v += sre[p*8+g] * ci[o2*8+g];
    float s2 = fmaxf(v, 0.f) * gd2v;
    for (int c = 0; c < C1; c++) {
        float s = s1[c] + s2;
        float w = w1[t*C1 + c] / (1.f + expf(-s));
        g_dyn1h[(b*C2 + t)*C1 + c] = __half_as_ushort(__float2half(w));
    }
}

// ---------------- K3X: fused fc1 (x fp32 -> fp16 mma, all 4 og) + GELU -> padded h ----------------
// smem: A fp16 128x64 sw128 [0,16K) | B fp16 256x64 sw128 [16K,48K) | pack 128x68 u16 [48K, +17408)
__global__ __launch_bounds__(256) void k3x(const float* __restrict__ x) {
    extern __shared__ __align__(128) unsigned char sdx[];
    uint32_t aA = smem_u32(sdx);
    uint32_t aB = aA + 16384;
    unsigned short* sh16 = (unsigned short*)(sdx + 49152);
    int l0 = blockIdx.x * 128, b = blockIdx.y;
    int t = threadIdx.x;

    // stage B: all 256 o-rows x 64 c via cp.async
    const unsigned short* wb = g_dyn1h + (size_t)b * C2 * 64;
    #pragma unroll
    for (int j = 0; j < 8; j++) {
        int i = t + j * 256;
        int row = i >> 3, u = i & 7;
        cp16(aB + sw128((uint32_t)(row*128 + u*16)), wb + (size_t)row*64 + u*8);
    }
    asm volatile("cp.async.commit_group;" ::: "memory");

    // stage A: c-pair loads -> half2 u32 swizzled stores (16 steps)
    const float* xb = x + (size_t)b * C1 * HW + l0;
    #pragma unroll
    for (int j = 0; j < 16; j++) {
        int idx = j * 256 + t;           // 0..4095
        int cp = idx >> 7;               // c-pair 0..31
        int l  = idx & 127;
        float v0 = xb[(size_t)(2*cp)     * HW + l];
        float v1 = xb[(size_t)(2*cp + 1) * HW + l];
        __half2 h2 = __floats2half2_rn(v0, v1);
        uint32_t so = sw128((uint32_t)(l*128 + cp*4));
        *(uint32_t*)(sdx + so) = *(uint32_t*)&h2;
    }
    asm volatile("cp.async.wait_group 0;" ::: "memory");
    __syncthreads();

    int w = t >> 5, lane = t & 31;
    // A fragments once (shared across all og)
    uint32_t a[4][4];
    #pragma unroll
    for (int kk = 0; kk < 4; kk++) {
        uint32_t aoff = sw128((uint32_t)((16*w + (lane & 15)) * 128 + kk * 32 + (lane >> 4) * 16));
        ldm4(a[kk], aA + aoff);
    }

    // precompute epilogue copy addresses (og-invariant)
    size_t dstbase[8];
    int srcoff[8];
    #pragma unroll
    for (int j = 0; j < 8; j++) {
        int i = t + j * 256;             // 0..2047
        int row = i >> 4, q = i & 15;
        int l = l0 + row;
        int y = l / 96;
        int lp = y * WP + (l - y * 96);
        dstbase[j] = ((size_t)b*HPAD + GOFF + lp) * 64 + q;
        srcoff[j]  = row*68 + q*4;
    }

    int r = lane >> 2, c2 = (lane & 3) * 2;
    #pragma unroll 1
    for (int og = 0; og < 4; og++) {
        float acc[8][4];
        #pragma unroll
        for (int i = 0; i < 8; i++)
            #pragma unroll
            for (int j = 0; j < 4; j++) acc[i][j] = 0.f;
        #pragma unroll
        for (int kk = 0; kk < 4; kk++) {
            #pragma unroll
            for (int p = 0; p < 4; p++) {
                uint32_t boff = sw128((uint32_t)((og*64 + p*16 + (lane & 15)) * 128
                                                 + kk * 32 + (lane >> 4) * 16));
                uint32_t bb[4];
                ldm4(bb, aB + boff);
                mma16816h(acc[2*p],   a[kk], bb[0], bb[2]);
                mma16816h(acc[2*p+1], a[kk], bb[1], bb[3]);
            }
        }
        // pack: GELU + half2 u32 stores, [l][o_local] stride 68
        #pragma unroll
        for (int p = 0; p < 4; p++)
            #pragma unroll
            for (int q = 0; q < 2; q++) {
                int n = p*16 + q*8 + c2;
                #pragma unroll
                for (int hv = 0; hv < 2; hv++) {
                    int m = 16*w + r + hv*8;
                    __half2 h2 = __floats2half2_rn(gelu_f(acc[2*p+q][hv*2]),
                                                   gelu_f(acc[2*p+q][hv*2 + 1]));
                    *(uint32_t*)&sh16[m*68 + n] = *(uint32_t*)&h2;
                }
            }
        __syncthreads();
        #pragma unroll
        for (int j = 0; j < 8; j++) {
            uint2 vh = *(const uint2*)&sh16[srcoff[j]];
            ((uint2*)g_hth)[dstbase[j] + og*16] = vh;
        }
        __syncthreads();
    }
}

// ---------------- K4a: partial 3x3 adaptive max over fp16 h (stride WP) ----------------
__global__ void k4a_part() {
    int bx = blockIdx.x;                 // 24 = ybin(3) * ys(8)
    int b = blockIdx.y;
    int ybin = bx >> 3, ys = bx & 7;
    int y0 = ybin * 32 + ys * 4;
    int t = threadIdx.x;                 // c
    const unsigned short* base = g_hth + ((size_t)b * HPAD + GOFF) * 256 + t;
    float m[3] = {-FLT_MAX, -FLT_MAX, -FLT_MAX};
    #pragma unroll
    for (int yy = 0; yy < 4; yy++) {
        const unsigned short* rp = base + (size_t)(y0 + yy) * WP * 256;
        #pragma unroll
        for (int xb = 0; xb < 3; xb++) {
            float mm = m[xb];
            #pragma unroll 8
            for (int xx = 0; xx < 32; xx++)
                mm = fmaxf(mm, __half2float(__ushort_as_half(rp[(size_t)(xb*32 + xx) * 256])));
            m[xb] = mm;
        }
    }
    #pragma unroll
    for (int xb = 0; xb < 3; xb++)
        g_p4[((((size_t)b*3 + ybin)*8 + ys)*3 + xb)*256 + t] = m[xb];
}

// ---------------- K45: fused partial-reduce + fc2 gating scalars ----------------
__global__ void k45(const float* __restrict__ ce_w, const float* __restrict__ gd_w,
                    const float* __restrict__ gd2_w, const float* __restrict__ ci_w) {
    int b = blockIdx.x, t = threadIdx.x;           // t = c (256)
    __shared__ float sre[C2][5];
    float glv[9];
    #pragma unroll
    for (int ybin = 0; ybin < 3; ybin++)
        #pragma unroll
        for (int xbin = 0; xbin < 3; xbin++) {
            float m = -FLT_MAX;
            #pragma unroll
            for (int ys = 0; ys < 8; ys++)
                m = fmaxf(m, g_p4[((((size_t)b*3 + ybin)*8 + ys)*3 + xbin)*256 + t]);
            glv[ybin*3 + xbin] = m;
        }
    {
        float rc[5];
        #pragma unroll
        for (int n = 0; n < 5; n++) {
            float v = 0.f;
            #pragma unroll
            for (int k = 0; k < 9; k++) v += glv[k] * ce_w[n*9 + k];
            rc[n] = fmaxf(v, 0.f);
            sre[t][n] = rc[n];
        }
        #pragma unroll
        for (int k = 0; k < 9; k++) {
            float v = 0.f;
            #pragma unroll
            for (int n = 0; n < 5; n++) v += rc[n] * gd_w[k*5 + n];
            g_outA[(b*C2 + t)*9 + k] = v;
        }
    }
    __syncthreads();
    if (t < C3) {
        int p = t >> 1, o2 = t & 1;
        float v[5];
        #pragma unroll
        for (int n = 0; n < 5; n++) {
            float s = 0.f;
            #pragma unroll
            for (int g = 0; g < 8; g++) s += sre[p*8+g][n] * ci_w[o2*8 + g];
            v[n] = fmaxf(s, 0.f);
        }
        #pragma unroll
        for (int k = 0; k < 9; k++) {
            float s = 0.f;
            #pragma unroll
            for (int n = 0; n < 5; n++) s += v[n] * gd2_w[k*5 + n];
            g_ocp2[(b*C3 + t)*9 + k] = s;
        }
    }
}

// ---------------- K5b: fp16 dynamic fc2 weights, [b][tap][o][c] ----------------
__global__ void k5b(const float* __restrict__ w2) {
    int idx = blockIdx.x * 256 + threadIdx.x;       // ((b*9+k)*64+o)*256 + c
    int c = idx & 255;
    int o = (idx >> 8) & 63;
    int t2 = idx >> 14;
    int k = t2 % 9, b = t2 / 9;
    float s = g_outA[(b*C2 + c)*9 + k] + g_ocp2[(b*C3 + o)*9 + k];
    float w = w2[(o*C2 + c)*9 + k] / (1.f + expf(-s));
    g_w2h[idx] = __half_as_ushort(__float2half(w));
}

// ---------------- K6: fc2 fp16 mma; padded-stride shifts (exact), 37 tiles x B = 1 wave ----------------
#define ABUF 29056                         // 454 rows x 64B (c=32)
#define BBUF 36864                         // 9 taps x 64 o x 64B
#define STG6 (ABUF + BBUF)                 // 65920 per stage, x2 = 131840
__device__ __forceinline__ void stage6(uint32_t base, const unsigned short* hh,
        int b, int l0, int cb, int t) {
    const unsigned short* ha = hh + (size_t)(l0 - GOFF) * 256 + cb * 32;
    #pragma unroll
    for (int j = 0; j < 4; j++) {
        int i = t + j * 512;
        if (i < 1816) {
            int row = i >> 2, u = i & 3;
            cp16(base + sw64((uint32_t)(row*64 + u*16)), ha + (size_t)row*256 + u*8);
        }
    }
    const unsigned short* wb = g_w2h + (size_t)b * 9 * 64 * 256 + cb * 32;
    #pragma unroll
    for (int j = 0; j < 5; j++) {
        int i = t + j * 512;
        if (i < 2304) {
            int row2 = i >> 2, u = i & 3;
            int tap = row2 >> 6, o = row2 & 63;
            cp16(base + ABUF + tap*4096 + sw64((uint32_t)(o*64 + u*16)),
                 wb + (size_t)row2 * 256 + u*8);
        }
    }
}

__global__ __launch_bounds__(512, 1) void k6_fc2(float* __restrict__ out) {
    extern __shared__ __align__(128) unsigned char sdy[];
    uint32_t base0 = smem_u32(sdy);
    int tile = blockIdx.x, b = blockIdx.y;
    int l0 = tile * 256, t = threadIdx.x;
    int w = t >> 5, lane = t & 31;

    const unsigned short* hh = g_hth + ((size_t)b * HPAD + GOFF) * 256;

    float acc[8][4];
    #pragma unroll
    for (int i = 0; i < 8; i++)
        #pragma unroll
        for (int j = 0; j < 4; j++) acc[i][j] = 0.f;

    stage6(base0, hh, b, l0, 0, t);
    asm volatile("cp.async.commit_group;" ::: "memory");

    for (int cb = 0; cb < 8; cb++) {
        if (cb < 7) {
            stage6(base0 + ((cb + 1) & 1) * STG6, hh, b, l0, cb + 1, t);
            asm volatile("cp.async.commit_group;" ::: "memory");
            asm volatile("cp.async.wait_group 1;" ::: "memory");
        } else {
            asm volatile("cp.async.wait_group 0;" ::: "memory");
        }
        __syncthreads();
        uint32_t aA = base0 + (cb & 1) * STG6;
        uint32_t aB0 = aA + ABUF;
        #pragma unroll
        for (int tap = 0; tap < 9; tap++) {
            const int d = (tap / 3) * WP + (tap % 3);
            #pragma unroll
            for (int kk = 0; kk < 2; kk++) {
                uint32_t a[4];
                uint32_t aoff = sw64((uint32_t)((16*w + (lane & 15) + d) * 64
                                                + kk * 32 + (lane >> 4) * 16));
                ldm4(a, aA + aoff);
                #pragma unroll
                for (int p = 0; p < 4; p++) {
                    uint32_t boff = aB0 + tap*4096
                        + sw64((uint32_t)((p*16 + (lane & 15)) * 64 + kk * 32 + (lane >> 4) * 16));
                    uint32_t bb[4];
                    ldm4(bb, boff);
                    mma16816h(acc[2*p],   a, bb[0], bb[2]);
                    mma16816h(acc[2*p+1], a, bb[1], bb[3]);
                }
            }
        }
        __syncthreads();
    }

    float* sD = (float*)sdy;
    int r = lane >> 2, c2 = (lane & 3) * 2;
    int lbase = 16*w;
    #pragma unroll
    for (int q = 0; q < 8; q++) {
        int o = q * 8 + c2;
        sD[(o    ) * 260 + lbase + r    ] = acc[q][0];
        sD[(o + 1) * 260 + lbase + r    ] = acc[q][1];
        sD[(o    ) * 260 + lbase + r + 8] = acc[q][2];
        sD[(o + 1) * 260 + lbase + r + 8] = acc[q][3];
    }
    __syncthreads();
    float* ob = out + (size_t)b * C3 * HW;
    #pragma unroll 4
    for (int i = t; i < 16384; i += 512) {
        int o = i >> 8, ll = i & 255;
        int lp = l0 + ll;
        if (lp < LP) {
            int y = lp / WP;
            int x = lp - y * WP;
            if (x < 96)
                ob[(size_t)o * HW + y * 96 + x] = sD[o * 260 + ll];
        }
    }
}

// ---------------- launch ----------------
extern "C" void kernel_launch(void* const* d_in, const int* in_sizes, int n_in,
                              void* d_out, int out_size) {
    const float* x     = (const float*)d_in[0];
    const float* w1    = (const float*)d_in[1];
    const float* f1ce  = (const float*)d_in[2];
    const float* f1gd  = (const float*)d_in[3];
    const float* f1gd2 = (const float*)d_in[4];
    const float* f1ci  = (const float*)d_in[5];
    const float* w2    = (const float*)d_in[6];
    const float* f2ce  = (const float*)d_in[7];
    const float* f2gd  = (const float*)d_in[8];
    const float* f2gd2 = (const float*)d_in[9];
    const float* f2ci  = (const float*)d_in[10];
    float* out = (float*)d_out;

    cudaFuncSetAttribute(k6_fc2, cudaFuncAttributeMaxDynamicSharedMemorySize, 2*STG6);
    cudaFuncSetAttribute(k3x, cudaFuncAttributeMaxDynamicSharedMemorySize, 66560);

    k0_zero<<<(B*576*32 + 255)/256, 256>>>();
    k1_gl1<<<B*C1, 256>>>(x);
    k2_dyn1<<<B, 256>>>(w1, f1ce, f1gd, f1gd2, f1ci);
    k3x<<<dim3(HW/128, B), 256, 66560>>>(x);
    k4a_part<<<dim3(24, B), 256>>>();
    k45<<<B, 256>>>(f2ce, f2gd, f2gd2, f2ci);
    k5b<<<(B*9*C3*C2)/256, 256>>>(w2);
    k6_fc2<<<dim3(37, B), 512, 2*STG6>>>(out);
}